// round 9
// baseline (speedup 1.0000x reference)
#include <cuda_runtime.h>
#include <cstdint>
#include <math_constants.h>

// ---------------------------------------------------------------------------
// Problem constants
// ---------------------------------------------------------------------------
#define B_  96
#define Q_  96
#define V_  197
#define T_  77
#define DK  768   // DV == DT
#define E_  512

#define VROWS (B_ * V_)   // 18912
#define TROWS (Q_ * T_)   // 7392

// Scratch for projected+normalized token embeddings (alloc-free: __device__ globals)
__device__ float g_vtok[VROWS * E_];   // [B*V, 512]
__device__ float g_ttok[TROWS * E_];   // [Q*T, 512]

// ---------------------------------------------------------------------------
// GEMM: Y[M, 512] = X[M, 768] @ W[512, 768]^T + bias
// 64x64 tile, BK=16, 256 threads, 4x4 per-thread register tile.
// ---------------------------------------------------------------------------
__global__ __launch_bounds__(256) void gemm_bias_kernel(
    const float* __restrict__ X, const float* __restrict__ W,
    const float* __restrict__ bias, float* __restrict__ Y, int M)
{
    __shared__ __align__(16) float As[16][68];
    __shared__ __align__(16) float Bs[16][68];

    const int tid = threadIdx.x;
    const int tx  = tid & 15;     // N direction
    const int ty  = tid >> 4;     // M direction
    const int m0  = blockIdx.x * 64;
    const int n0  = blockIdx.y * 64;

    float acc[4][4] = {};

    const int lrow = tid >> 2;          // 0..63
    const int lkq  = (tid & 3) << 2;    // 0,4,8,12

    for (int k0 = 0; k0 < DK; k0 += 16) {
        // Load A tile (64 rows x 16 k), transpose to [k][m]
        {
            float4 v = make_float4(0.f, 0.f, 0.f, 0.f);
            const int gr = m0 + lrow;
            if (gr < M)
                v = *(const float4*)(X + (size_t)gr * DK + k0 + lkq);
            As[lkq + 0][lrow] = v.x;
            As[lkq + 1][lrow] = v.y;
            As[lkq + 2][lrow] = v.z;
            As[lkq + 3][lrow] = v.w;
        }
        // Load B tile: W rows n0..n0+63 (N=512 divisible by 64, no guard)
        {
            const float4 w4 = *(const float4*)(W + (size_t)(n0 + lrow) * DK + k0 + lkq);
            Bs[lkq + 0][lrow] = w4.x;
            Bs[lkq + 1][lrow] = w4.y;
            Bs[lkq + 2][lrow] = w4.z;
            Bs[lkq + 3][lrow] = w4.w;
        }
        __syncthreads();

        #pragma unroll
        for (int k = 0; k < 16; k++) {
            const float4 a4 = *(const float4*)&As[k][ty * 4];
            const float4 b4 = *(const float4*)&Bs[k][tx * 4];
            const float a[4] = {a4.x, a4.y, a4.z, a4.w};
            const float b[4] = {b4.x, b4.y, b4.z, b4.w};
            #pragma unroll
            for (int i = 0; i < 4; i++)
                #pragma unroll
                for (int j = 0; j < 4; j++)
                    acc[i][j] = fmaf(a[i], b[j], acc[i][j]);
        }
        __syncthreads();
    }

    #pragma unroll
    for (int i = 0; i < 4; i++) {
        const int r = m0 + ty * 4 + i;
        if (r < M) {
            #pragma unroll
            for (int j = 0; j < 4; j++) {
                const int c = n0 + tx * 4 + j;
                Y[(size_t)r * E_ + c] = acc[i][j] + bias[c];
            }
        }
    }
}

// ---------------------------------------------------------------------------
// In-place row L2 normalization: x / max(||x||, 1e-12). One warp per 512-row.
// ---------------------------------------------------------------------------
__global__ __launch_bounds__(256) void l2norm_rows_kernel(float* __restrict__ Y, int M)
{
    const int row  = blockIdx.x * 8 + (threadIdx.x >> 5);
    const int lane = threadIdx.x & 31;
    if (row >= M) return;

    float4* p = (float4*)(Y + (size_t)row * E_);
    float4 v[4];
    float ss = 0.f;
    #pragma unroll
    for (int t = 0; t < 4; t++) {
        v[t] = p[lane + 32 * t];
        ss += v[t].x * v[t].x + v[t].y * v[t].y + v[t].z * v[t].z + v[t].w * v[t].w;
    }
    #pragma unroll
    for (int off = 16; off; off >>= 1)
        ss += __shfl_xor_sync(0xffffffffu, ss, off);

    const float inv = 1.f / fmaxf(sqrtf(ss), 1e-12f);
    #pragma unroll
    for (int t = 0; t < 4; t++) {
        v[t].x *= inv; v[t].y *= inv; v[t].z *= inv; v[t].w *= inv;
        p[lane + 32 * t] = v[t];
    }
}

// ---------------------------------------------------------------------------
// Fused similarity + masked max reductions.
// One CTA per (b,q): S[197,77] = vtok[b] @ ttok[q]^T over K=512.
// 512 threads, per-thread 7(M, stride 32) x 5(N, stride 16) register tile.
// ---------------------------------------------------------------------------
#define SBK 32
#define PA  225   // odd pitch, covers Mpad=224
#define PB  81    // odd pitch, covers Npad=80

__device__ __forceinline__ void atomicMaxFloatS(float* addr, float val)
{
    int* ai = (int*)addr;
    int old = *ai;
    while (__int_as_float(old) < val) {
        const int assumed = old;
        old = atomicCAS(ai, assumed, __float_as_int(val));
        if (old == assumed) break;
    }
}

__global__ __launch_bounds__(512, 2) void sim_kernel(
    const float* __restrict__ vtok, const float* __restrict__ ttok,
    const int* __restrict__ tlen,
    float* __restrict__ out_t2v, float* __restrict__ out_v2t)
{
    __shared__ float As[SBK * PA];
    __shared__ float Bs[SBK * PB];
    __shared__ float colmax_s[80];
    __shared__ float red[32];

    const int q = blockIdx.x;
    const int b = blockIdx.y;
    const int tid = threadIdx.x;
    const int tx  = tid & 15;    // N (cols / text tokens)
    const int ty  = tid >> 4;    // M (rows / visual tokens), 0..31

    float acc[7][5];
    #pragma unroll
    for (int i = 0; i < 7; i++)
        #pragma unroll
        for (int j = 0; j < 5; j++) acc[i][j] = 0.f;

    const float* vb = vtok + (size_t)b * V_ * E_;
    const float* tq = ttok + (size_t)q * T_ * E_;

    for (int k0 = 0; k0 < E_; k0 += SBK) {
        for (int idx = tid; idx < V_ * SBK; idx += 512) {
            const int v  = idx >> 5;
            const int kk = idx & 31;
            As[kk * PA + v] = vb[v * E_ + k0 + kk];
        }
        for (int idx = tid; idx < T_ * SBK; idx += 512) {
            const int t  = idx >> 5;
            const int kk = idx & 31;
            Bs[kk * PB + t] = tq[t * E_ + k0 + kk];
        }
        __syncthreads();

        #pragma unroll
        for (int kk = 0; kk < SBK; kk++) {
            float a[7], bb[5];
            #pragma unroll
            for (int i = 0; i < 7; i++) a[i] = As[kk * PA + ty + 32 * i];
            #pragma unroll
            for (int j = 0; j < 5; j++) bb[j] = Bs[kk * PB + tx + 16 * j];
            #pragma unroll
            for (int i = 0; i < 7; i++)
                #pragma unroll
                for (int j = 0; j < 5; j++)
                    acc[i][j] = fmaf(a[i], bb[j], acc[i][j]);
        }
        __syncthreads();
    }

    const int len = tlen[q];

    if (tid < 80) colmax_s[tid] = -CUDART_INF_F;
    __syncthreads();

    // --- v2t: for each visual row, max over t of (masked logit), then sum/V ---
    float rowsum = 0.f;
    #pragma unroll
    for (int i = 0; i < 7; i++) {
        const int r = ty + 32 * i;
        float m = -CUDART_INF_F;
        #pragma unroll
        for (int j = 0; j < 5; j++) {
            const int c = tx + 16 * j;
            if (c < T_) {
                const float s  = acc[i][j];
                const float mv = (c < len) ? s : 0.0f;   // logits * mask, then max
                m = fmaxf(m, mv);
            }
        }
        // reduce across the 16 tx lanes (xor over bits 0..3 stays within same ty)
        #pragma unroll
        for (int off = 8; off; off >>= 1)
            m = fmaxf(m, __shfl_xor_sync(0xffffffffu, m, off));
        if (tx == 0 && r < V_) rowsum += m;
    }
    if (tx == 0) red[ty] = rowsum;

    // --- t2v: for each valid text col, max over v; invalid cols contribute 0 ---
    #pragma unroll
    for (int j = 0; j < 5; j++) {
        const int c = tx + 16 * j;
        if (c < T_ && c < len) {
            float cm = -CUDART_INF_F;
            #pragma unroll
            for (int i = 0; i < 7; i++) {
                const int r = ty + 32 * i;
                if (r < V_) cm = fmaxf(cm, acc[i][j]);
            }
            atomicMaxFloatS(&colmax_s[c], cm);
        }
    }
    __syncthreads();

    if (tid == 0) {
        float s = 0.f;
        #pragma unroll
        for (int t = 0; t < 32; t++) s += red[t];
        out_v2t[b * Q_ + q] = s / (float)V_;

        float s2 = 0.f;
        for (int c = 0; c < len; c++) s2 += colmax_s[c];
        out_t2v[b * Q_ + q] = s2 / (float)len;
    }
}

// ---------------------------------------------------------------------------
// kernel_launch
// Inputs (metadata order):
//  0 visual_cls [96,768]      1 visual_tokens [96,197,768]
//  2 textual_cls [96,768]     3 textual_tokens [96,77,768]
//  4 Wv_cls [512,768]  5 bv_cls [512]  6 Wt_cls [512,768]  7 bt_cls [512]
//  8 Wv_tok [512,768]  9 bv_tok [512] 10 Wt_tok [512,768] 11 bt_tok [512]
// 12 text_length [96] int32
// Output: v_cls(49152) | t_cls(49152) | t2v(9216) | v2t(9216)  fp32
// ---------------------------------------------------------------------------
extern "C" void kernel_launch(void* const* d_in, const int* in_sizes, int n_in,
                              void* d_out, int out_size)
{
    const float* visual_cls     = (const float*)d_in[0];
    const float* visual_tokens  = (const float*)d_in[1];
    const float* textual_cls    = (const float*)d_in[2];
    const float* textual_tokens = (const float*)d_in[3];
    const float* Wv_cls = (const float*)d_in[4];
    const float* bv_cls = (const float*)d_in[5];
    const float* Wt_cls = (const float*)d_in[6];
    const float* bt_cls = (const float*)d_in[7];
    const float* Wv_tok = (const float*)d_in[8];
    const float* bv_tok = (const float*)d_in[9];
    const float* Wt_tok = (const float*)d_in[10];
    const float* bt_tok = (const float*)d_in[11];
    const int*   tlen   = (const int*)d_in[12];

    float* out   = (float*)d_out;
    float* o_vcls = out;                       // 96*512
    float* o_tcls = out + 96 * 512;            // 96*512
    float* o_t2v  = out + 2 * 96 * 512;        // 96*96
    float* o_v2t  = o_t2v + 96 * 96;           // 96*96

    float* vtok = nullptr;
    float* ttok = nullptr;
    cudaGetSymbolAddress((void**)&vtok, g_vtok);
    cudaGetSymbolAddress((void**)&ttok, g_ttok);

    // 1. cls projections straight to output (no normalization)
    {
        dim3 grid((96 + 63) / 64, E_ / 64);
        gemm_bias_kernel<<<grid, 256>>>(visual_cls,  Wv_cls, bv_cls, o_vcls, 96);
        gemm_bias_kernel<<<grid, 256>>>(textual_cls, Wt_cls, bt_cls, o_tcls, 96);
    }
    // 2. token projections to scratch
    {
        dim3 gv((VROWS + 63) / 64, E_ / 64);
        gemm_bias_kernel<<<gv, 256>>>(visual_tokens, Wv_tok, bv_tok, vtok, VROWS);
        dim3 gt((TROWS + 63) / 64, E_ / 64);
        gemm_bias_kernel<<<gt, 256>>>(textual_tokens, Wt_tok, bt_tok, ttok, TROWS);
    }
    // 3. in-place L2 normalization
    l2norm_rows_kernel<<<(VROWS + 7) / 8, 256>>>(vtok, VROWS);
    l2norm_rows_kernel<<<(TROWS + 7) / 8, 256>>>(ttok, TROWS);

    // 4. fused similarity + masked max reductions
    {
        dim3 grid(Q_, B_);
        sim_kernel<<<grid, 512>>>(vtok, ttok, tlen, o_t2v, o_v2t);
    }
}

// round 11
// speedup vs baseline: 5.7539x; 5.7539x over previous
#include <cuda_runtime.h>
#include <cuda_bf16.h>
#include <cstdint>
#include <math_constants.h>

// ---------------------------------------------------------------------------
// Problem constants
// ---------------------------------------------------------------------------
#define B_  96
#define Q_  96
#define V_  197
#define T_  77
#define DK  768
#define E_  512

#define VROWS (B_ * V_)   // 18912
#define TROWS (Q_ * T_)   // 7392

// Scratch (alloc-free: __device__ globals)
__device__ float g_vtok[VROWS * E_];
__device__ float g_ttok[TROWS * E_];
__device__ __align__(16) __nv_bfloat16 g_vtok_bf[VROWS * E_];
__device__ __align__(16) __nv_bfloat16 g_ttok_bf[TROWS * E_];

__device__ __forceinline__ uint32_t smem_u32(const void* p) {
    uint32_t a;
    asm("{ .reg .u64 t; cvta.to.shared.u64 t, %1; cvt.u32.u64 %0, t; }"
        : "=r"(a) : "l"(p));
    return a;
}

// ===========================================================================
// GEMM: Y[M, 512] = X[M, 768] @ W[512, 768]^T + bias  (fp32 SIMT)
// ===========================================================================
__global__ __launch_bounds__(256) void gemm_bias_kernel(
    const float* __restrict__ X, const float* __restrict__ W,
    const float* __restrict__ bias, float* __restrict__ Y, int M)
{
    __shared__ __align__(16) float As[16][68];
    __shared__ __align__(16) float Bs[16][68];

    const int tid = threadIdx.x;
    const int tx  = tid & 15;
    const int ty  = tid >> 4;
    const int m0  = blockIdx.x * 64;
    const int n0  = blockIdx.y * 64;

    float acc[4][4] = {};

    const int lrow = tid >> 2;
    const int lkq  = (tid & 3) << 2;

    for (int k0 = 0; k0 < DK; k0 += 16) {
        {
            float4 v = make_float4(0.f, 0.f, 0.f, 0.f);
            const int gr = m0 + lrow;
            if (gr < M)
                v = *(const float4*)(X + (size_t)gr * DK + k0 + lkq);
            As[lkq + 0][lrow] = v.x;
            As[lkq + 1][lrow] = v.y;
            As[lkq + 2][lrow] = v.z;
            As[lkq + 3][lrow] = v.w;
        }
        {
            const float4 w4 = *(const float4*)(W + (size_t)(n0 + lrow) * DK + k0 + lkq);
            Bs[lkq + 0][lrow] = w4.x;
            Bs[lkq + 1][lrow] = w4.y;
            Bs[lkq + 2][lrow] = w4.z;
            Bs[lkq + 3][lrow] = w4.w;
        }
        __syncthreads();

        #pragma unroll
        for (int k = 0; k < 16; k++) {
            const float4 a4 = *(const float4*)&As[k][ty * 4];
            const float4 b4 = *(const float4*)&Bs[k][tx * 4];
            const float a[4] = {a4.x, a4.y, a4.z, a4.w};
            const float b[4] = {b4.x, b4.y, b4.z, b4.w};
            #pragma unroll
            for (int i = 0; i < 4; i++)
                #pragma unroll
                for (int j = 0; j < 4; j++)
                    acc[i][j] = fmaf(a[i], b[j], acc[i][j]);
        }
        __syncthreads();
    }

    #pragma unroll
    for (int i = 0; i < 4; i++) {
        const int r = m0 + ty * 4 + i;
        if (r < M) {
            #pragma unroll
            for (int j = 0; j < 4; j++) {
                const int c = n0 + tx * 4 + j;
                Y[(size_t)r * E_ + c] = acc[i][j] + bias[c];
            }
        }
    }
}

// ===========================================================================
// L2 normalization: fp32 in -> normalized bf16 out. One warp per row.
// ===========================================================================
__global__ __launch_bounds__(256) void l2norm_bf16_kernel(
    const float* __restrict__ Y, __nv_bfloat16* __restrict__ O, int M)
{
    const int row  = blockIdx.x * 8 + (threadIdx.x >> 5);
    const int lane = threadIdx.x & 31;
    if (row >= M) return;

    const float4* p = (const float4*)(Y + (size_t)row * E_);
    float4 v[4];
    float ss = 0.f;
    #pragma unroll
    for (int t = 0; t < 4; t++) {
        v[t] = p[lane + 32 * t];
        ss += v[t].x * v[t].x + v[t].y * v[t].y + v[t].z * v[t].z + v[t].w * v[t].w;
    }
    #pragma unroll
    for (int off = 16; off; off >>= 1)
        ss += __shfl_xor_sync(0xffffffffu, ss, off);

    const float inv = 1.f / fmaxf(sqrtf(ss), 1e-12f);

    __nv_bfloat162* o2 = (__nv_bfloat162*)(O + (size_t)row * E_);
    #pragma unroll
    for (int t = 0; t < 4; t++) {
        const int e = lane + 32 * t;
        o2[e * 2 + 0] = __floats2bfloat162_rn(v[t].x * inv, v[t].y * inv);
        o2[e * 2 + 1] = __floats2bfloat162_rn(v[t].z * inv, v[t].w * inv);
    }
}

// ===========================================================================
// mma.sync bf16 fused similarity kernel. One CTA per (b, q).
// D[256(pad 197) x 80(pad 77)] = Vb @ Tq^T, K=512, BK=32.
// 8 warps: 4 (M) x 2 (N). Per warp: M=64 (4 x m16), N=40 (5 x n8).
// Epilogue reductions fully in registers/shfl.
// ===========================================================================
#define SPITCH 80   // bytes per smem row (64B data + 16B pad -> ldmatrix conflict-free)

__device__ __forceinline__ void mma_16816(float* c, const uint32_t* a,
                                          const uint32_t* b) {
    asm volatile(
        "mma.sync.aligned.m16n8k16.row.col.f32.bf16.bf16.f32 "
        "{%0,%1,%2,%3}, {%4,%5,%6,%7}, {%8,%9}, {%0,%1,%2,%3};"
        : "+f"(c[0]), "+f"(c[1]), "+f"(c[2]), "+f"(c[3])
        : "r"(a[0]), "r"(a[1]), "r"(a[2]), "r"(a[3]), "r"(b[0]), "r"(b[1]));
}

__global__ __launch_bounds__(256, 2) void sim_mma_kernel(
    const __nv_bfloat16* __restrict__ vtok, const __nv_bfloat16* __restrict__ ttok,
    const int* __restrict__ tlen,
    float* __restrict__ out_t2v, float* __restrict__ out_v2t)
{
    __shared__ __align__(16) char sA[256 * SPITCH];   // 20480 B
    __shared__ __align__(16) char sB[80 * SPITCH];    //  6400 B
    __shared__ float rowmax2[256][2];
    __shared__ float colmax2[80][4];
    __shared__ float warpsum[8];
    __shared__ float t2vpart[3];

    const int tid  = threadIdx.x;
    const int wid  = tid >> 5;
    const int lane = tid & 31;
    const int q = blockIdx.x;
    const int b = blockIdx.y;

    const int warpM0 = (wid >> 1) * 64;
    const int warpN0 = (wid & 1) * 40;
    const int lane4  = lane >> 2;   // 0..7
    const int lanem  = lane & 3;    // 0..3

    const uint32_t sAu = smem_u32(sA);
    const uint32_t sBu = smem_u32(sB);

    const __nv_bfloat16* vb = vtok + (size_t)b * V_ * E_;
    const __nv_bfloat16* tq = ttok + (size_t)q * T_ * E_;

    float acc[4][5][4];
    #pragma unroll
    for (int mt = 0; mt < 4; mt++)
        #pragma unroll
        for (int nt = 0; nt < 5; nt++)
            #pragma unroll
            for (int r = 0; r < 4; r++) acc[mt][nt][r] = 0.f;

    // ldmatrix lane address components (within-chunk)
    const uint32_t a_row = (uint32_t)(lane & 15);          // row within m16 tile
    const uint32_t a_col = (uint32_t)((lane >> 4) << 3);   // +8 k for lanes 16-31
    const uint32_t b_row = (uint32_t)(lane & 7);           // row within n8 tile
    const uint32_t b_col = (uint32_t)(((lane >> 3) & 1) << 3);

    for (int k0 = 0; k0 < E_; k0 += 32) {
        __syncthreads();
        // Load A chunk: 256 rows x 32 bf16 (rows >= 197 zeroed)
        #pragma unroll
        for (int t = 0; t < 4; t++) {
            const int idx = tid + t * 256;      // 0..1023
            const int row = idx >> 2, seg = idx & 3;
            uint4 val = make_uint4(0, 0, 0, 0);
            if (row < V_)
                val = *(const uint4*)(vb + (size_t)row * E_ + k0 + seg * 8);
            *(uint4*)(sA + row * SPITCH + seg * 16) = val;
        }
        // Load B chunk: 80 rows x 32 bf16 (rows >= 77 zeroed)
        {
            const int idx = tid; // 0..255 covers 64 rows
            const int row = idx >> 2, seg = idx & 3;
            uint4 val = make_uint4(0, 0, 0, 0);
            if (row < T_)
                val = *(const uint4*)(tq + (size_t)row * E_ + k0 + seg * 8);
            *(uint4*)(sB + row * SPITCH + seg * 16) = val;
        }
        if (tid < 64) {
            const int idx = tid + 256;
            const int row = idx >> 2, seg = idx & 3;
            uint4 val = make_uint4(0, 0, 0, 0);
            if (row < T_)
                val = *(const uint4*)(tq + (size_t)row * E_ + k0 + seg * 8);
            *(uint4*)(sB + row * SPITCH + seg * 16) = val;
        }
        __syncthreads();

        #pragma unroll
        for (int ks = 0; ks < 2; ks++) {
            const uint32_t kloc = ks * 16;

            uint32_t af[4][4];
            #pragma unroll
            for (int mt = 0; mt < 4; mt++) {
                const uint32_t addr = sAu
                    + (warpM0 + mt * 16 + a_row) * SPITCH
                    + (kloc + a_col) * 2;
                asm volatile(
                    "ldmatrix.sync.aligned.m8n8.x4.shared.b16 {%0,%1,%2,%3}, [%4];"
                    : "=r"(af[mt][0]), "=r"(af[mt][1]),
                      "=r"(af[mt][2]), "=r"(af[mt][3])
                    : "r"(addr));
            }
            uint32_t bf[5][2];
            #pragma unroll
            for (int nt = 0; nt < 5; nt++) {
                const uint32_t addr = sBu
                    + (warpN0 + nt * 8 + b_row) * SPITCH
                    + (kloc + b_col) * 2;
                asm volatile(
                    "ldmatrix.sync.aligned.m8n8.x2.shared.b16 {%0,%1}, [%2];"
                    : "=r"(bf[nt][0]), "=r"(bf[nt][1])
                    : "r"(addr));
            }
            #pragma unroll
            for (int mt = 0; mt < 4; mt++)
                #pragma unroll
                for (int nt = 0; nt < 5; nt++)
                    mma_16816(acc[mt][nt], af[mt], bf[nt]);
        }
    }

    // ---- Epilogue: masked reductions straight from the accumulator layout ----
    // acc[mt][nt][h*2+j]: row = warpM0 + mt*16 + lane4 + 8h,
    //                     col = warpN0 + nt*8 + lanem*2 + j
    const int len = tlen[q];

    // Row-max over this warp's 40 cols (mask: c<len -> s; c in [len,77) -> 0; c>=77 -> -inf)
    #pragma unroll
    for (int mt = 0; mt < 4; mt++) {
        #pragma unroll
        for (int h = 0; h < 2; h++) {
            float m = -CUDART_INF_F;
            #pragma unroll
            for (int nt = 0; nt < 5; nt++) {
                #pragma unroll
                for (int j = 0; j < 2; j++) {
                    const int c = warpN0 + nt * 8 + lanem * 2 + j;
                    const float s = acc[mt][nt][h * 2 + j];
                    const float mv = (c < len) ? s
                                   : ((c < T_) ? 0.0f : -CUDART_INF_F);
                    m = fmaxf(m, mv);
                }
            }
            m = fmaxf(m, __shfl_xor_sync(0xffffffffu, m, 1));
            m = fmaxf(m, __shfl_xor_sync(0xffffffffu, m, 2));
            if (lanem == 0)
                rowmax2[warpM0 + mt * 16 + lane4 + 8 * h][wid & 1] = m;
        }
    }

    // Col-max over this warp's 64 rows (rows >= 197 -> -inf)
    #pragma unroll
    for (int nt = 0; nt < 5; nt++) {
        #pragma unroll
        for (int j = 0; j < 2; j++) {
            float m = -CUDART_INF_F;
            #pragma unroll
            for (int mt = 0; mt < 4; mt++) {
                #pragma unroll
                for (int h = 0; h < 2; h++) {
                    const int r = warpM0 + mt * 16 + lane4 + 8 * h;
                    const float s = acc[mt][nt][h * 2 + j];
                    m = fmaxf(m, (r < V_) ? s : -CUDART_INF_F);
                }
            }
            m = fmaxf(m, __shfl_xor_sync(0xffffffffu, m, 4));
            m = fmaxf(m, __shfl_xor_sync(0xffffffffu, m, 8));
            m = fmaxf(m, __shfl_xor_sync(0xffffffffu, m, 16));
            if (lane < 4) {
                const int c = warpN0 + nt * 8 + lane * 2 + j;
                colmax2[c][wid >> 1] = m;
            }
        }
    }
    __syncthreads();

    // v2t: sum over valid rows of max across the 2 N-warps, / V
    {
        float s = 0.f;
        if (tid < V_) s = fmaxf(rowmax2[tid][0], rowmax2[tid][1]);
        #pragma unroll
        for (int off = 16; off; off >>= 1)
            s += __shfl_xor_sync(0xffffffffu, s, off);
        if (lane == 0) warpsum[wid] = s;
    }
    // t2v partials: cols < len, max across 4 M-warps
    if (wid < 3) {
        const int c = wid * 32 + lane;
        float s = 0.f;
        if (c < len) {
            const float m01 = fmaxf(colmax2[c][0], colmax2[c][1]);
            const float m23 = fmaxf(colmax2[c][2], colmax2[c][3]);
            s = fmaxf(m01, m23);
        }
        #pragma unroll
        for (int off = 16; off; off >>= 1)
            s += __shfl_xor_sync(0xffffffffu, s, off);
        if (lane == 0) t2vpart[wid] = s;
    }
    __syncthreads();

    if (tid == 0) {
        float s1 = 0.f;
        #pragma unroll
        for (int t = 0; t < 8; t++) s1 += warpsum[t];
        out_v2t[b * Q_ + q] = s1 / (float)V_;
        out_t2v[b * Q_ + q] = (t2vpart[0] + t2vpart[1] + t2vpart[2]) / (float)len;
    }
}

// ===========================================================================
// kernel_launch
// ===========================================================================
extern "C" void kernel_launch(void* const* d_in, const int* in_sizes, int n_in,
                              void* d_out, int out_size)
{
    const float* visual_cls     = (const float*)d_in[0];
    const float* visual_tokens  = (const float*)d_in[1];
    const float* textual_cls    = (const float*)d_in[2];
    const float* textual_tokens = (const float*)d_in[3];
    const float* Wv_cls = (const float*)d_in[4];
    const float* bv_cls = (const float*)d_in[5];
    const float* Wt_cls = (const float*)d_in[6];
    const float* bt_cls = (const float*)d_in[7];
    const float* Wv_tok = (const float*)d_in[8];
    const float* bv_tok = (const float*)d_in[9];
    const float* Wt_tok = (const float*)d_in[10];
    const float* bt_tok = (const float*)d_in[11];
    const int*   tlen   = (const int*)d_in[12];

    float* out    = (float*)d_out;
    float* o_vcls = out;
    float* o_tcls = out + 96 * 512;
    float* o_t2v  = out + 2 * 96 * 512;
    float* o_v2t  = o_t2v + 96 * 96;

    float* vtok = nullptr;
    float* ttok = nullptr;
    __nv_bfloat16* vtok_bf = nullptr;
    __nv_bfloat16* ttok_bf = nullptr;
    cudaGetSymbolAddress((void**)&vtok, g_vtok);
    cudaGetSymbolAddress((void**)&ttok, g_ttok);
    cudaGetSymbolAddress((void**)&vtok_bf, g_vtok_bf);
    cudaGetSymbolAddress((void**)&ttok_bf, g_ttok_bf);

    // 1. cls projections -> output
    {
        dim3 grid((96 + 63) / 64, E_ / 64);
        gemm_bias_kernel<<<grid, 256>>>(visual_cls,  Wv_cls, bv_cls, o_vcls, 96);
        gemm_bias_kernel<<<grid, 256>>>(textual_cls, Wt_cls, bt_cls, o_tcls, 96);
    }
    // 2. token projections -> fp32 scratch
    {
        dim3 gv((VROWS + 63) / 64, E_ / 64);
        gemm_bias_kernel<<<gv, 256>>>(visual_tokens, Wv_tok, bv_tok, vtok, VROWS);
        dim3 gt((TROWS + 63) / 64, E_ / 64);
        gemm_bias_kernel<<<gt, 256>>>(textual_tokens, Wt_tok, bt_tok, ttok, TROWS);
    }
    // 3. L2 normalize -> bf16 scratch
    l2norm_bf16_kernel<<<(VROWS + 7) / 8, 256>>>(vtok, vtok_bf, VROWS);
    l2norm_bf16_kernel<<<(TROWS + 7) / 8, 256>>>(ttok, ttok_bf, TROWS);

    // 4. mma.sync fused similarity + reductions
    {
        dim3 grid(Q_, B_);
        sim_mma_kernel<<<grid, 256>>>(vtok_bf, ttok_bf, tlen, o_t2v, o_v2t);
    }
}

// round 12
// speedup vs baseline: 5.7828x; 1.0050x over previous
#include <cuda_runtime.h>
#include <cuda_bf16.h>
#include <cstdint>
#include <math_constants.h>

// ---------------------------------------------------------------------------
// Problem constants
// ---------------------------------------------------------------------------
#define B_  96
#define Q_  96
#define V_  197
#define T_  77
#define DK  768
#define E_  512

#define VROWS (B_ * V_)   // 18912
#define TROWS (Q_ * T_)   // 7392

// Scratch (alloc-free: __device__ globals)
__device__ float g_vtok[VROWS * E_];
__device__ float g_ttok[TROWS * E_];
__device__ __align__(16) __nv_bfloat16 g_vtok_bf[VROWS * E_];
__device__ __align__(16) __nv_bfloat16 g_ttok_bf[TROWS * E_];
__device__ __align__(16) __nv_bfloat16 g_wv_bf[E_ * DK];
__device__ __align__(16) __nv_bfloat16 g_wt_bf[E_ * DK];

__device__ __forceinline__ uint32_t smem_u32(const void* p) {
    uint32_t a;
    asm("{ .reg .u64 t; cvta.to.shared.u64 t, %1; cvt.u32.u64 %0, t; }"
        : "=r"(a) : "l"(p));
    return a;
}

__device__ __forceinline__ void mma_16816(float* c, const uint32_t* a,
                                          const uint32_t* b) {
    asm volatile(
        "mma.sync.aligned.m16n8k16.row.col.f32.bf16.bf16.f32 "
        "{%0,%1,%2,%3}, {%4,%5,%6,%7}, {%8,%9}, {%0,%1,%2,%3};"
        : "+f"(c[0]), "+f"(c[1]), "+f"(c[2]), "+f"(c[3])
        : "r"(a[0]), "r"(a[1]), "r"(a[2]), "r"(a[3]), "r"(b[0]), "r"(b[1]));
}

// ===========================================================================
// fp32 -> bf16 elementwise (for weights)
// ===========================================================================
__global__ __launch_bounds__(256) void f32_to_bf16_kernel(
    const float* __restrict__ src, __nv_bfloat16* __restrict__ dst, int n4)
{
    const int i = blockIdx.x * 256 + threadIdx.x;
    if (i < n4) {
        const float4 f = ((const float4*)src)[i];
        ((__nv_bfloat162*)dst)[i * 2 + 0] = __floats2bfloat162_rn(f.x, f.y);
        ((__nv_bfloat162*)dst)[i * 2 + 1] = __floats2bfloat162_rn(f.z, f.w);
    }
}

// ===========================================================================
// fp32 SIMT GEMM (kept for the small cls projections -> exact outputs)
// Y[M, 512] = X[M, 768] @ W[512, 768]^T + bias
// ===========================================================================
__global__ __launch_bounds__(256) void gemm_bias_kernel(
    const float* __restrict__ X, const float* __restrict__ W,
    const float* __restrict__ bias, float* __restrict__ Y, int M)
{
    __shared__ __align__(16) float As[16][68];
    __shared__ __align__(16) float Bs[16][68];

    const int tid = threadIdx.x;
    const int tx  = tid & 15;
    const int ty  = tid >> 4;
    const int m0  = blockIdx.x * 64;
    const int n0  = blockIdx.y * 64;

    float acc[4][4] = {};

    const int lrow = tid >> 2;
    const int lkq  = (tid & 3) << 2;

    for (int k0 = 0; k0 < DK; k0 += 16) {
        {
            float4 v = make_float4(0.f, 0.f, 0.f, 0.f);
            const int gr = m0 + lrow;
            if (gr < M)
                v = *(const float4*)(X + (size_t)gr * DK + k0 + lkq);
            As[lkq + 0][lrow] = v.x;
            As[lkq + 1][lrow] = v.y;
            As[lkq + 2][lrow] = v.z;
            As[lkq + 3][lrow] = v.w;
        }
        {
            const float4 w4 = *(const float4*)(W + (size_t)(n0 + lrow) * DK + k0 + lkq);
            Bs[lkq + 0][lrow] = w4.x;
            Bs[lkq + 1][lrow] = w4.y;
            Bs[lkq + 2][lrow] = w4.z;
            Bs[lkq + 3][lrow] = w4.w;
        }
        __syncthreads();

        #pragma unroll
        for (int k = 0; k < 16; k++) {
            const float4 a4 = *(const float4*)&As[k][ty * 4];
            const float4 b4 = *(const float4*)&Bs[k][tx * 4];
            const float a[4] = {a4.x, a4.y, a4.z, a4.w};
            const float b[4] = {b4.x, b4.y, b4.z, b4.w};
            #pragma unroll
            for (int i = 0; i < 4; i++)
                #pragma unroll
                for (int j = 0; j < 4; j++)
                    acc[i][j] = fmaf(a[i], b[j], acc[i][j]);
        }
        __syncthreads();
    }

    #pragma unroll
    for (int i = 0; i < 4; i++) {
        const int r = m0 + ty * 4 + i;
        if (r < M) {
            #pragma unroll
            for (int j = 0; j < 4; j++) {
                const int c = n0 + tx * 4 + j;
                Y[(size_t)r * E_ + c] = acc[i][j] + bias[c];
            }
        }
    }
}

// ===========================================================================
// bf16 mma.sync GEMM for token projections.
// Y[M, 512] = bf16(X[M, 768]) @ Wbf[512, 768]^T + bias   (fp32 out)
// CTA tile 128x128, BK=32, 8 warps (4M x 2N), warp tile 32x64 (2 x 8 mma tiles).
// X converted fp32->bf16 inline during the smem fill.
// ===========================================================================
#define GP 80   // smem row pitch (bytes): 64B data + 16B pad

__global__ __launch_bounds__(256, 2) void gemm_bf16_kernel(
    const float* __restrict__ X, const __nv_bfloat16* __restrict__ Wbf,
    const float* __restrict__ bias, float* __restrict__ Y, int M)
{
    __shared__ __align__(16) char sA[128 * GP];
    __shared__ __align__(16) char sB[128 * GP];

    const int tid  = threadIdx.x;
    const int wid  = tid >> 5;
    const int lane = tid & 31;
    const int m0 = blockIdx.x * 128;
    const int n0 = blockIdx.y * 128;

    const int warpM0 = (wid >> 1) * 32;
    const int warpN0 = (wid & 1) * 64;

    const uint32_t sAu = smem_u32(sA);
    const uint32_t sBu = smem_u32(sB);

    float acc[2][8][4];
    #pragma unroll
    for (int mt = 0; mt < 2; mt++)
        #pragma unroll
        for (int nt = 0; nt < 8; nt++)
            #pragma unroll
            for (int r = 0; r < 4; r++) acc[mt][nt][r] = 0.f;

    // ldmatrix lane address components
    const uint32_t a_row  = (uint32_t)(lane & 15);
    const uint32_t a_col  = (uint32_t)((lane >> 4) << 3);
    const uint32_t bw_row = (uint32_t)((lane & 7) | ((lane >> 4) << 3));
    const uint32_t bw_col = (uint32_t)(((lane >> 3) & 1) << 3);

    for (int k0 = 0; k0 < DK; k0 += 32) {
        __syncthreads();
        // A: 128 rows x 32 k, fp32 -> bf16 inline
        #pragma unroll
        for (int t = 0; t < 2; t++) {
            const int u   = tid + t * 256;   // 0..511
            const int row = u >> 2, seg = u & 3;
            const int gr  = m0 + row;
            uint4 val = make_uint4(0, 0, 0, 0);
            if (gr < M) {
                const float4 f0 = *(const float4*)(X + (size_t)gr * DK + k0 + seg * 8);
                const float4 f1 = *(const float4*)(X + (size_t)gr * DK + k0 + seg * 8 + 4);
                __nv_bfloat162 h0 = __floats2bfloat162_rn(f0.x, f0.y);
                __nv_bfloat162 h1 = __floats2bfloat162_rn(f0.z, f0.w);
                __nv_bfloat162 h2 = __floats2bfloat162_rn(f1.x, f1.y);
                __nv_bfloat162 h3 = __floats2bfloat162_rn(f1.z, f1.w);
                val.x = *(uint32_t*)&h0; val.y = *(uint32_t*)&h1;
                val.z = *(uint32_t*)&h2; val.w = *(uint32_t*)&h3;
            }
            *(uint4*)(sA + row * GP + seg * 16) = val;
        }
        // B: weights (N=512 divisible by 128, no guard)
        #pragma unroll
        for (int t = 0; t < 2; t++) {
            const int u   = tid + t * 256;
            const int row = u >> 2, seg = u & 3;
            const uint4 val = *(const uint4*)(Wbf + (size_t)(n0 + row) * DK + k0 + seg * 8);
            *(uint4*)(sB + row * GP + seg * 16) = val;
        }
        __syncthreads();

        #pragma unroll
        for (int ks = 0; ks < 2; ks++) {
            const uint32_t kloc = ks * 16;

            uint32_t af[2][4];
            #pragma unroll
            for (int mt = 0; mt < 2; mt++) {
                const uint32_t addr = sAu
                    + (warpM0 + mt * 16 + a_row) * GP + (kloc + a_col) * 2;
                asm volatile(
                    "ldmatrix.sync.aligned.m8n8.x4.shared.b16 {%0,%1,%2,%3}, [%4];"
                    : "=r"(af[mt][0]), "=r"(af[mt][1]),
                      "=r"(af[mt][2]), "=r"(af[mt][3])
                    : "r"(addr));
            }
            uint32_t bf[4][4];   // bf[nt2] = {tile(2*nt2).b0,b1, tile(2*nt2+1).b0,b1}
            #pragma unroll
            for (int nt2 = 0; nt2 < 4; nt2++) {
                const uint32_t addr = sBu
                    + (warpN0 + nt2 * 16 + bw_row) * GP + (kloc + bw_col) * 2;
                asm volatile(
                    "ldmatrix.sync.aligned.m8n8.x4.shared.b16 {%0,%1,%2,%3}, [%4];"
                    : "=r"(bf[nt2][0]), "=r"(bf[nt2][1]),
                      "=r"(bf[nt2][2]), "=r"(bf[nt2][3])
                    : "r"(addr));
            }
            #pragma unroll
            for (int mt = 0; mt < 2; mt++)
                #pragma unroll
                for (int nt2 = 0; nt2 < 4; nt2++) {
                    mma_16816(acc[mt][nt2 * 2 + 0], af[mt], &bf[nt2][0]);
                    mma_16816(acc[mt][nt2 * 2 + 1], af[mt], &bf[nt2][2]);
                }
        }
    }

    // Epilogue: row = m0+warpM0+mt*16+(lane>>2)+8h, col = n0+warpN0+nt*8+(lane&3)*2+j
    const int lane4 = lane >> 2;
    const int lanem = lane & 3;
    #pragma unroll
    for (int mt = 0; mt < 2; mt++) {
        #pragma unroll
        for (int h = 0; h < 2; h++) {
            const int r = m0 + warpM0 + mt * 16 + lane4 + 8 * h;
            if (r < M) {
                #pragma unroll
                for (int nt = 0; nt < 8; nt++) {
                    const int c = n0 + warpN0 + nt * 8 + lanem * 2;
                    float2 o;
                    o.x = acc[mt][nt][h * 2 + 0] + bias[c];
                    o.y = acc[mt][nt][h * 2 + 1] + bias[c + 1];
                    *(float2*)(Y + (size_t)r * E_ + c) = o;
                }
            }
        }
    }
}

// ===========================================================================
// L2 normalization: fp32 in -> normalized bf16 out. One warp per row.
// ===========================================================================
__global__ __launch_bounds__(256) void l2norm_bf16_kernel(
    const float* __restrict__ Y, __nv_bfloat16* __restrict__ O, int M)
{
    const int row  = blockIdx.x * 8 + (threadIdx.x >> 5);
    const int lane = threadIdx.x & 31;
    if (row >= M) return;

    const float4* p = (const float4*)(Y + (size_t)row * E_);
    float4 v[4];
    float ss = 0.f;
    #pragma unroll
    for (int t = 0; t < 4; t++) {
        v[t] = p[lane + 32 * t];
        ss += v[t].x * v[t].x + v[t].y * v[t].y + v[t].z * v[t].z + v[t].w * v[t].w;
    }
    #pragma unroll
    for (int off = 16; off; off >>= 1)
        ss += __shfl_xor_sync(0xffffffffu, ss, off);

    const float inv = 1.f / fmaxf(sqrtf(ss), 1e-12f);

    __nv_bfloat162* o2 = (__nv_bfloat162*)(O + (size_t)row * E_);
    #pragma unroll
    for (int t = 0; t < 4; t++) {
        const int e = lane + 32 * t;
        o2[e * 2 + 0] = __floats2bfloat162_rn(v[t].x * inv, v[t].y * inv);
        o2[e * 2 + 1] = __floats2bfloat162_rn(v[t].z * inv, v[t].w * inv);
    }
}

// ===========================================================================
// mma.sync bf16 fused similarity kernel. One CTA per (b, q).  (unchanged)
// ===========================================================================
#define SPITCH 80

__global__ __launch_bounds__(256, 2) void sim_mma_kernel(
    const __nv_bfloat16* __restrict__ vtok, const __nv_bfloat16* __restrict__ ttok,
    const int* __restrict__ tlen,
    float* __restrict__ out_t2v, float* __restrict__ out_v2t)
{
    __shared__ __align__(16) char sA[256 * SPITCH];
    __shared__ __align__(16) char sB[80 * SPITCH];
    __shared__ float rowmax2[256][2];
    __shared__ float colmax2[80][4];
    __shared__ float warpsum[8];
    __shared__ float t2vpart[3];

    const int tid  = threadIdx.x;
    const int wid  = tid >> 5;
    const int lane = tid & 31;
    const int q = blockIdx.x;
    const int b = blockIdx.y;

    const int warpM0 = (wid >> 1) * 64;
    const int warpN0 = (wid & 1) * 40;
    const int lane4  = lane >> 2;
    const int lanem  = lane & 3;

    const uint32_t sAu = smem_u32(sA);
    const uint32_t sBu = smem_u32(sB);

    const __nv_bfloat16* vb = vtok + (size_t)b * V_ * E_;
    const __nv_bfloat16* tq = ttok + (size_t)q * T_ * E_;

    float acc[4][5][4];
    #pragma unroll
    for (int mt = 0; mt < 4; mt++)
        #pragma unroll
        for (int nt = 0; nt < 5; nt++)
            #pragma unroll
            for (int r = 0; r < 4; r++) acc[mt][nt][r] = 0.f;

    const uint32_t a_row = (uint32_t)(lane & 15);
    const uint32_t a_col = (uint32_t)((lane >> 4) << 3);
    const uint32_t b_row = (uint32_t)(lane & 7);
    const uint32_t b_col = (uint32_t)(((lane >> 3) & 1) << 3);

    for (int k0 = 0; k0 < E_; k0 += 32) {
        __syncthreads();
        #pragma unroll
        for (int t = 0; t < 4; t++) {
            const int idx = tid + t * 256;
            const int row = idx >> 2, seg = idx & 3;
            uint4 val = make_uint4(0, 0, 0, 0);
            if (row < V_)
                val = *(const uint4*)(vb + (size_t)row * E_ + k0 + seg * 8);
            *(uint4*)(sA + row * SPITCH + seg * 16) = val;
        }
        {
            const int idx = tid;
            const int row = idx >> 2, seg = idx & 3;
            uint4 val = make_uint4(0, 0, 0, 0);
            if (row < T_)
                val = *(const uint4*)(tq + (size_t)row * E_ + k0 + seg * 8);
            *(uint4*)(sB + row * SPITCH + seg * 16) = val;
        }
        if (tid < 64) {
            const int idx = tid + 256;
            const int row = idx >> 2, seg = idx & 3;
            uint4 val = make_uint4(0, 0, 0, 0);
            if (row < T_)
                val = *(const uint4*)(tq + (size_t)row * E_ + k0 + seg * 8);
            *(uint4*)(sB + row * SPITCH + seg * 16) = val;
        }
        __syncthreads();

        #pragma unroll
        for (int ks = 0; ks < 2; ks++) {
            const uint32_t kloc = ks * 16;

            uint32_t af[4][4];
            #pragma unroll
            for (int mt = 0; mt < 4; mt++) {
                const uint32_t addr = sAu
                    + (warpM0 + mt * 16 + a_row) * SPITCH + (kloc + a_col) * 2;
                asm volatile(
                    "ldmatrix.sync.aligned.m8n8.x4.shared.b16 {%0,%1,%2,%3}, [%4];"
                    : "=r"(af[mt][0]), "=r"(af[mt][1]),
                      "=r"(af[mt][2]), "=r"(af[mt][3])
                    : "r"(addr));
            }
            uint32_t bfr[5][2];
            #pragma unroll
            for (int nt = 0; nt < 5; nt++) {
                const uint32_t addr = sBu
                    + (warpN0 + nt * 8 + b_row) * SPITCH + (kloc + b_col) * 2;
                asm volatile(
                    "ldmatrix.sync.aligned.m8n8.x2.shared.b16 {%0,%1}, [%2];"
                    : "=r"(bfr[nt][0]), "=r"(bfr[nt][1])
                    : "r"(addr));
            }
            #pragma unroll
            for (int mt = 0; mt < 4; mt++)
                #pragma unroll
                for (int nt = 0; nt < 5; nt++)
                    mma_16816(acc[mt][nt], af[mt], bfr[nt]);
        }
    }

    const int len = tlen[q];

    #pragma unroll
    for (int mt = 0; mt < 4; mt++) {
        #pragma unroll
        for (int h = 0; h < 2; h++) {
            float m = -CUDART_INF_F;
            #pragma unroll
            for (int nt = 0; nt < 5; nt++) {
                #pragma unroll
                for (int j = 0; j < 2; j++) {
                    const int c = warpN0 + nt * 8 + lanem * 2 + j;
                    const float s = acc[mt][nt][h * 2 + j];
                    const float mv = (c < len) ? s
                                   : ((c < T_) ? 0.0f : -CUDART_INF_F);
                    m = fmaxf(m, mv);
                }
            }
            m = fmaxf(m, __shfl_xor_sync(0xffffffffu, m, 1));
            m = fmaxf(m, __shfl_xor_sync(0xffffffffu, m, 2));
            if (lanem == 0)
                rowmax2[warpM0 + mt * 16 + lane4 + 8 * h][wid & 1] = m;
        }
    }

    #pragma unroll
    for (int nt = 0; nt < 5; nt++) {
        #pragma unroll
        for (int j = 0; j < 2; j++) {
            float m = -CUDART_INF_F;
            #pragma unroll
            for (int mt = 0; mt < 4; mt++) {
                #pragma unroll
                for (int h = 0; h < 2; h++) {
                    const int r = warpM0 + mt * 16 + lane4 + 8 * h;
                    const float s = acc[mt][nt][h * 2 + j];
                    m = fmaxf(m, (r < V_) ? s : -CUDART_INF_F);
                }
            }
            m = fmaxf(m, __shfl_xor_sync(0xffffffffu, m, 4));
            m = fmaxf(m, __shfl_xor_sync(0xffffffffu, m, 8));
            m = fmaxf(m, __shfl_xor_sync(0xffffffffu, m, 16));
            if (lane < 4) {
                const int c = warpN0 + nt * 8 + lane * 2 + j;
                colmax2[c][wid >> 1] = m;
            }
        }
    }
    __syncthreads();

    {
        float s = 0.f;
        if (tid < V_) s = fmaxf(rowmax2[tid][0], rowmax2[tid][1]);
        #pragma unroll
        for (int off = 16; off; off >>= 1)
            s += __shfl_xor_sync(0xffffffffu, s, off);
        if (lane == 0) warpsum[wid] = s;
    }
    if (wid < 3) {
        const int c = wid * 32 + lane;
        float s = 0.f;
        if (c < len) {
            const float m01 = fmaxf(colmax2[c][0], colmax2[c][1]);
            const float m23 = fmaxf(colmax2[c][2], colmax2[c][3]);
            s = fmaxf(m01, m23);
        }
        #pragma unroll
        for (int off = 16; off; off >>= 1)
            s += __shfl_xor_sync(0xffffffffu, s, off);
        if (lane == 0) t2vpart[wid] = s;
    }
    __syncthreads();

    if (tid == 0) {
        float s1 = 0.f;
        #pragma unroll
        for (int t = 0; t < 8; t++) s1 += warpsum[t];
        out_v2t[b * Q_ + q] = s1 / (float)V_;
        out_t2v[b * Q_ + q] = (t2vpart[0] + t2vpart[1] + t2vpart[2]) / (float)len;
    }
}

// ===========================================================================
// kernel_launch
// ===========================================================================
extern "C" void kernel_launch(void* const* d_in, const int* in_sizes, int n_in,
                              void* d_out, int out_size)
{
    const float* visual_cls     = (const float*)d_in[0];
    const float* visual_tokens  = (const float*)d_in[1];
    const float* textual_cls    = (const float*)d_in[2];
    const float* textual_tokens = (const float*)d_in[3];
    const float* Wv_cls = (const float*)d_in[4];
    const float* bv_cls = (const float*)d_in[5];
    const float* Wt_cls = (const float*)d_in[6];
    const float* bt_cls = (const float*)d_in[7];
    const float* Wv_tok = (const float*)d_in[8];
    const float* bv_tok = (const float*)d_in[9];
    const float* Wt_tok = (const float*)d_in[10];
    const float* bt_tok = (const float*)d_in[11];
    const int*   tlen   = (const int*)d_in[12];

    float* out    = (float*)d_out;
    float* o_vcls = out;
    float* o_tcls = out + 96 * 512;
    float* o_t2v  = out + 2 * 96 * 512;
    float* o_v2t  = o_t2v + 96 * 96;

    float* vtok = nullptr;
    float* ttok = nullptr;
    __nv_bfloat16 *vtok_bf = nullptr, *ttok_bf = nullptr;
    __nv_bfloat16 *wv_bf = nullptr, *wt_bf = nullptr;
    cudaGetSymbolAddress((void**)&vtok, g_vtok);
    cudaGetSymbolAddress((void**)&ttok, g_ttok);
    cudaGetSymbolAddress((void**)&vtok_bf, g_vtok_bf);
    cudaGetSymbolAddress((void**)&ttok_bf, g_ttok_bf);
    cudaGetSymbolAddress((void**)&wv_bf, g_wv_bf);
    cudaGetSymbolAddress((void**)&wt_bf, g_wt_bf);

    // 0. token weights -> bf16
    {
        const int n4 = E_ * DK / 4;   // 98304
        f32_to_bf16_kernel<<<(n4 + 255) / 256, 256>>>(Wv_tok, wv_bf, n4);
        f32_to_bf16_kernel<<<(n4 + 255) / 256, 256>>>(Wt_tok, wt_bf, n4);
    }
    // 1. cls projections -> output (exact fp32)
    {
        dim3 grid((96 + 63) / 64, E_ / 64);
        gemm_bias_kernel<<<grid, 256>>>(visual_cls,  Wv_cls, bv_cls, o_vcls, 96);
        gemm_bias_kernel<<<grid, 256>>>(textual_cls, Wt_cls, bt_cls, o_tcls, 96);
    }
    // 2. token projections -> fp32 scratch, via bf16 tensor-core GEMM
    {
        dim3 gv((VROWS + 127) / 128, E_ / 128);
        gemm_bf16_kernel<<<gv, 256>>>(visual_tokens, wv_bf, bv_tok, vtok, VROWS);
        dim3 gt((TROWS + 127) / 128, E_ / 128);
        gemm_bf16_kernel<<<gt, 256>>>(textual_tokens, wt_bf, bt_tok, ttok, TROWS);
    }
    // 3. L2 normalize -> bf16 scratch
    l2norm_bf16_kernel<<<(VROWS + 7) / 8, 256>>>(vtok, vtok_bf, VROWS);
    l2norm_bf16_kernel<<<(TROWS + 7) / 8, 256>>>(ttok, ttok_bf, TROWS);

    // 4. mma.sync fused similarity + reductions
    {
        dim3 grid(Q_, B_);
        sim_mma_kernel<<<grid, 256>>>(vtok_bf, ttok_bf, tlen, o_t2v, o_v2t);
    }
}

// round 14
// speedup vs baseline: 9.2175x; 1.5939x over previous
#include <cuda_runtime.h>
#include <cuda_bf16.h>
#include <cstdint>
#include <math_constants.h>

// ---------------------------------------------------------------------------
// Problem constants
// ---------------------------------------------------------------------------
#define B_  96
#define Q_  96
#define V_  197
#define T_  77
#define DK  768
#define E_  512

#define VROWS (B_ * V_)   // 18912
#define TROWS (Q_ * T_)   // 7392

// Scratch (alloc-free: __device__ globals)
__device__ float g_vtok[VROWS * E_];
__device__ float g_ttok[TROWS * E_];
__device__ __align__(16) __nv_bfloat16 g_vtok_bf[VROWS * E_];
__device__ __align__(16) __nv_bfloat16 g_ttok_bf[TROWS * E_];
__device__ __align__(16) __nv_bfloat16 g_wv_bf[E_ * DK];
__device__ __align__(16) __nv_bfloat16 g_wt_bf[E_ * DK];

__device__ __forceinline__ uint32_t smem_u32(const void* p) {
    uint32_t a;
    asm("{ .reg .u64 t; cvta.to.shared.u64 t, %1; cvt.u32.u64 %0, t; }"
        : "=r"(a) : "l"(p));
    return a;
}

__device__ __forceinline__ void mma_16816(float* c, const uint32_t* a,
                                          const uint32_t* b) {
    asm volatile(
        "mma.sync.aligned.m16n8k16.row.col.f32.bf16.bf16.f32 "
        "{%0,%1,%2,%3}, {%4,%5,%6,%7}, {%8,%9}, {%0,%1,%2,%3};"
        : "+f"(c[0]), "+f"(c[1]), "+f"(c[2]), "+f"(c[3])
        : "r"(a[0]), "r"(a[1]), "r"(a[2]), "r"(a[3]), "r"(b[0]), "r"(b[1]));
}

// ===========================================================================
// fp32 -> bf16 elementwise (for weights)
// ===========================================================================
__global__ __launch_bounds__(256) void f32_to_bf16_kernel(
    const float* __restrict__ src, __nv_bfloat16* __restrict__ dst, int n4)
{
    const int i = blockIdx.x * 256 + threadIdx.x;
    if (i < n4) {
        const float4 f = ((const float4*)src)[i];
        ((__nv_bfloat162*)dst)[i * 2 + 0] = __floats2bfloat162_rn(f.x, f.y);
        ((__nv_bfloat162*)dst)[i * 2 + 1] = __floats2bfloat162_rn(f.z, f.w);
    }
}

// ===========================================================================
// Merged cls projections (exact fp32), register-prefetch pipelined.
// blockIdx.z = 0: (X0,W0,b0,Y0)  = 1: (X1,W1,b1,Y1).  M = 96.
// ===========================================================================
__global__ __launch_bounds__(256) void gemm_cls_kernel(
    const float* __restrict__ X0, const float* __restrict__ W0,
    const float* __restrict__ bias0, float* __restrict__ Y0,
    const float* __restrict__ X1, const float* __restrict__ W1,
    const float* __restrict__ bias1, float* __restrict__ Y1)
{
    const float* X    = blockIdx.z ? X1 : X0;
    const float* W    = blockIdx.z ? W1 : W0;
    const float* bias = blockIdx.z ? bias1 : bias0;
    float*       Y    = blockIdx.z ? Y1 : Y0;
    const int M = 96;

    __shared__ __align__(16) float As[16][68];
    __shared__ __align__(16) float Bs[16][68];

    const int tid = threadIdx.x;
    const int tx  = tid & 15;
    const int ty  = tid >> 4;
    const int m0  = blockIdx.x * 64;
    const int n0  = blockIdx.y * 64;

    float acc[4][4] = {};

    const int lrow = tid >> 2;
    const int lkq  = (tid & 3) << 2;
    const int gr   = m0 + lrow;

    // prologue prefetch (chunk 0)
    float4 pa = make_float4(0.f, 0.f, 0.f, 0.f);
    if (gr < M) pa = *(const float4*)(X + (size_t)gr * DK + lkq);
    float4 pb = *(const float4*)(W + (size_t)(n0 + lrow) * DK + lkq);

    for (int k0 = 0; k0 < DK; k0 += 16) {
        As[lkq + 0][lrow] = pa.x; As[lkq + 1][lrow] = pa.y;
        As[lkq + 2][lrow] = pa.z; As[lkq + 3][lrow] = pa.w;
        Bs[lkq + 0][lrow] = pb.x; Bs[lkq + 1][lrow] = pb.y;
        Bs[lkq + 2][lrow] = pb.z; Bs[lkq + 3][lrow] = pb.w;
        __syncthreads();

        if (k0 + 16 < DK) {
            pa = make_float4(0.f, 0.f, 0.f, 0.f);
            if (gr < M) pa = *(const float4*)(X + (size_t)gr * DK + k0 + 16 + lkq);
            pb = *(const float4*)(W + (size_t)(n0 + lrow) * DK + k0 + 16 + lkq);
        }

        #pragma unroll
        for (int k = 0; k < 16; k++) {
            const float4 a4 = *(const float4*)&As[k][ty * 4];
            const float4 b4 = *(const float4*)&Bs[k][tx * 4];
            const float a[4] = {a4.x, a4.y, a4.z, a4.w};
            const float b[4] = {b4.x, b4.y, b4.z, b4.w};
            #pragma unroll
            for (int i = 0; i < 4; i++)
                #pragma unroll
                for (int j = 0; j < 4; j++)
                    acc[i][j] = fmaf(a[i], b[j], acc[i][j]);
        }
        __syncthreads();
    }

    #pragma unroll
    for (int i = 0; i < 4; i++) {
        const int r = m0 + ty * 4 + i;
        if (r < M) {
            #pragma unroll
            for (int j = 0; j < 4; j++) {
                const int c = n0 + tx * 4 + j;
                Y[(size_t)r * E_ + c] = acc[i][j] + bias[c];
            }
        }
    }
}

// ===========================================================================
// bf16 mma.sync GEMM for token projections, register-prefetch pipelined.
// Y[M, 512] = bf16(X[M, 768]) @ Wbf[512, 768]^T + bias   (fp32 out)
// CTA tile 128x128, BK=32, 8 warps (4M x 2N).
// ===========================================================================
#define GP 80   // smem row pitch (bytes)

__global__ __launch_bounds__(256, 2) void gemm_bf16_kernel(
    const float* __restrict__ X, const __nv_bfloat16* __restrict__ Wbf,
    const float* __restrict__ bias, float* __restrict__ Y, int M)
{
    __shared__ __align__(16) char sA[128 * GP];
    __shared__ __align__(16) char sB[128 * GP];

    const int tid  = threadIdx.x;
    const int wid  = tid >> 5;
    const int lane = tid & 31;
    const int m0 = blockIdx.x * 128;
    const int n0 = blockIdx.y * 128;

    const int warpM0 = (wid >> 1) * 32;
    const int warpN0 = (wid & 1) * 64;

    const uint32_t sAu = smem_u32(sA);
    const uint32_t sBu = smem_u32(sB);

    // (row, seg) slots handled by this thread (t = 0, 1)
    const int rowA[2] = { tid >> 2, (tid + 256) >> 2 };
    const int segA[2] = { tid & 3, (tid + 256) & 3 };

    float acc[2][8][4];
    #pragma unroll
    for (int mt = 0; mt < 2; mt++)
        #pragma unroll
        for (int nt = 0; nt < 8; nt++)
            #pragma unroll
            for (int r = 0; r < 4; r++) acc[mt][nt][r] = 0.f;

    const uint32_t a_row  = (uint32_t)(lane & 15);
    const uint32_t a_col  = (uint32_t)((lane >> 4) << 3);
    const uint32_t bw_row = (uint32_t)((lane & 7) | ((lane >> 4) << 3));
    const uint32_t bw_col = (uint32_t)(((lane >> 3) & 1) << 3);

    uint4 pA[2], pB[2];

    // prologue prefetch (chunk 0)
    #pragma unroll
    for (int t = 0; t < 2; t++) {
        const int gr = m0 + rowA[t];
        uint4 val = make_uint4(0, 0, 0, 0);
        if (gr < M) {
            const float4 f0 = *(const float4*)(X + (size_t)gr * DK + segA[t] * 8);
            const float4 f1 = *(const float4*)(X + (size_t)gr * DK + segA[t] * 8 + 4);
            __nv_bfloat162 h0 = __floats2bfloat162_rn(f0.x, f0.y);
            __nv_bfloat162 h1 = __floats2bfloat162_rn(f0.z, f0.w);
            __nv_bfloat162 h2 = __floats2bfloat162_rn(f1.x, f1.y);
            __nv_bfloat162 h3 = __floats2bfloat162_rn(f1.z, f1.w);
            val.x = *(uint32_t*)&h0; val.y = *(uint32_t*)&h1;
            val.z = *(uint32_t*)&h2; val.w = *(uint32_t*)&h3;
        }
        pA[t] = val;
        pB[t] = *(const uint4*)(Wbf + (size_t)(n0 + rowA[t]) * DK + segA[t] * 8);
    }

    for (int k0 = 0; k0 < DK; k0 += 32) {
        #pragma unroll
        for (int t = 0; t < 2; t++) {
            *(uint4*)(sA + rowA[t] * GP + segA[t] * 16) = pA[t];
            *(uint4*)(sB + rowA[t] * GP + segA[t] * 16) = pB[t];
        }
        __syncthreads();

        if (k0 + 32 < DK) {
            const int kn = k0 + 32;
            #pragma unroll
            for (int t = 0; t < 2; t++) {
                const int gr = m0 + rowA[t];
                uint4 val = make_uint4(0, 0, 0, 0);
                if (gr < M) {
                    const float4 f0 = *(const float4*)(X + (size_t)gr * DK + kn + segA[t] * 8);
                    const float4 f1 = *(const float4*)(X + (size_t)gr * DK + kn + segA[t] * 8 + 4);
                    __nv_bfloat162 h0 = __floats2bfloat162_rn(f0.x, f0.y);
                    __nv_bfloat162 h1 = __floats2bfloat162_rn(f0.z, f0.w);
                    __nv_bfloat162 h2 = __floats2bfloat162_rn(f1.x, f1.y);
                    __nv_bfloat162 h3 = __floats2bfloat162_rn(f1.z, f1.w);
                    val.x = *(uint32_t*)&h0; val.y = *(uint32_t*)&h1;
                    val.z = *(uint32_t*)&h2; val.w = *(uint32_t*)&h3;
                }
                pA[t] = val;
                pB[t] = *(const uint4*)(Wbf + (size_t)(n0 + rowA[t]) * DK + kn + segA[t] * 8);
            }
        }

        #pragma unroll
        for (int ks = 0; ks < 2; ks++) {
            const uint32_t kloc = ks * 16;

            uint32_t af[2][4];
            #pragma unroll
            for (int mt = 0; mt < 2; mt++) {
                const uint32_t addr = sAu
                    + (warpM0 + mt * 16 + a_row) * GP + (kloc + a_col) * 2;
                asm volatile(
                    "ldmatrix.sync.aligned.m8n8.x4.shared.b16 {%0,%1,%2,%3}, [%4];"
                    : "=r"(af[mt][0]), "=r"(af[mt][1]),
                      "=r"(af[mt][2]), "=r"(af[mt][3])
                    : "r"(addr));
            }
            uint32_t bfr[4][4];
            #pragma unroll
            for (int nt2 = 0; nt2 < 4; nt2++) {
                const uint32_t addr = sBu
                    + (warpN0 + nt2 * 16 + bw_row) * GP + (kloc + bw_col) * 2;
                asm volatile(
                    "ldmatrix.sync.aligned.m8n8.x4.shared.b16 {%0,%1,%2,%3}, [%4];"
                    : "=r"(bfr[nt2][0]), "=r"(bfr[nt2][1]),
                      "=r"(bfr[nt2][2]), "=r"(bfr[nt2][3])
                    : "r"(addr));
            }
            #pragma unroll
            for (int mt = 0; mt < 2; mt++)
                #pragma unroll
                for (int nt2 = 0; nt2 < 4; nt2++) {
                    mma_16816(acc[mt][nt2 * 2 + 0], af[mt], &bfr[nt2][0]);
                    mma_16816(acc[mt][nt2 * 2 + 1], af[mt], &bfr[nt2][2]);
                }
        }
        __syncthreads();
    }

    const int lane4 = lane >> 2;
    const int lanem = lane & 3;
    #pragma unroll
    for (int mt = 0; mt < 2; mt++) {
        #pragma unroll
        for (int h = 0; h < 2; h++) {
            const int r = m0 + warpM0 + mt * 16 + lane4 + 8 * h;
            if (r < M) {
                #pragma unroll
                for (int nt = 0; nt < 8; nt++) {
                    const int c = n0 + warpN0 + nt * 8 + lanem * 2;
                    float2 o;
                    o.x = acc[mt][nt][h * 2 + 0] + bias[c];
                    o.y = acc[mt][nt][h * 2 + 1] + bias[c + 1];
                    *(float2*)(Y + (size_t)r * E_ + c) = o;
                }
            }
        }
    }
}

// ===========================================================================
// L2 normalization: fp32 in -> normalized bf16 out. One warp per row.
// ===========================================================================
__global__ __launch_bounds__(256) void l2norm_bf16_kernel(
    const float* __restrict__ Y, __nv_bfloat16* __restrict__ O, int M)
{
    const int row  = blockIdx.x * 8 + (threadIdx.x >> 5);
    const int lane = threadIdx.x & 31;
    if (row >= M) return;

    const float4* p = (const float4*)(Y + (size_t)row * E_);
    float4 v[4];
    float ss = 0.f;
    #pragma unroll
    for (int t = 0; t < 4; t++) {
        v[t] = p[lane + 32 * t];
        ss += v[t].x * v[t].x + v[t].y * v[t].y + v[t].z * v[t].z + v[t].w * v[t].w;
    }
    #pragma unroll
    for (int off = 16; off; off >>= 1)
        ss += __shfl_xor_sync(0xffffffffu, ss, off);

    const float inv = 1.f / fmaxf(sqrtf(ss), 1e-12f);

    __nv_bfloat162* o2 = (__nv_bfloat162*)(O + (size_t)row * E_);
    #pragma unroll
    for (int t = 0; t < 4; t++) {
        const int e = lane + 32 * t;
        o2[e * 2 + 0] = __floats2bfloat162_rn(v[t].x * inv, v[t].y * inv);
        o2[e * 2 + 1] = __floats2bfloat162_rn(v[t].z * inv, v[t].w * inv);
    }
}

// ===========================================================================
// mma.sync bf16 fused similarity kernel, with text-length tile skipping.
// One CTA per (b, q). Columns (n8 tiles) at or beyond len are never computed;
// the reference's "masked -> 0" contribution to the row max is applied as a
// single 0-clamp at combine time when len < T.
// ===========================================================================
#define SPITCH 80

__global__ __launch_bounds__(256, 2) void sim_mma_kernel(
    const __nv_bfloat16* __restrict__ vtok, const __nv_bfloat16* __restrict__ ttok,
    const int* __restrict__ tlen,
    float* __restrict__ out_t2v, float* __restrict__ out_v2t)
{
    __shared__ __align__(16) char sA[256 * SPITCH];
    __shared__ __align__(16) char sB[80 * SPITCH];
    __shared__ float rowmax2[256][2];
    __shared__ float colmax2[80][4];
    __shared__ float warpsum[8];
    __shared__ float t2vpart[3];

    const int tid  = threadIdx.x;
    const int wid  = tid >> 5;
    const int lane = tid & 31;
    const int q = blockIdx.x;
    const int b = blockIdx.y;

    const int warpM0 = (wid >> 1) * 64;
    const int warpN0 = (wid & 1) * 40;
    const int lane4  = lane >> 2;
    const int lanem  = lane & 3;

    const int len = tlen[q];
    // number of n8 tiles this warp actually needs (CTA-uniform per N-half)
    const int dlen = len - warpN0;
    const int ntW  = (dlen <= 0) ? 0 : (dlen >= 40 ? 5 : ((dlen + 7) >> 3));

    const uint32_t sAu = smem_u32(sA);
    const uint32_t sBu = smem_u32(sB);

    const __nv_bfloat16* vb = vtok + (size_t)b * V_ * E_;
    const __nv_bfloat16* tq = ttok + (size_t)q * T_ * E_;

    float acc[4][5][4];
    #pragma unroll
    for (int mt = 0; mt < 4; mt++)
        #pragma unroll
        for (int nt = 0; nt < 5; nt++)
            #pragma unroll
            for (int r = 0; r < 4; r++) acc[mt][nt][r] = 0.f;

    const uint32_t a_row = (uint32_t)(lane & 15);
    const uint32_t a_col = (uint32_t)((lane >> 4) << 3);
    const uint32_t b_row = (uint32_t)(lane & 7);
    const uint32_t b_col = (uint32_t)(((lane >> 3) & 1) << 3);

    for (int k0 = 0; k0 < E_; k0 += 32) {
        __syncthreads();
        #pragma unroll
        for (int t = 0; t < 4; t++) {
            const int idx = tid + t * 256;
            const int row = idx >> 2, seg = idx & 3;
            uint4 val = make_uint4(0, 0, 0, 0);
            if (row < V_)
                val = *(const uint4*)(vb + (size_t)row * E_ + k0 + seg * 8);
            *(uint4*)(sA + row * SPITCH + seg * 16) = val;
        }
        {
            const int row = tid >> 2, seg = tid & 3;
            uint4 val = make_uint4(0, 0, 0, 0);
            if (row < T_)
                val = *(const uint4*)(tq + (size_t)row * E_ + k0 + seg * 8);
            *(uint4*)(sB + row * SPITCH + seg * 16) = val;
        }
        if (tid < 64) {
            const int idx = tid + 256;
            const int row = idx >> 2, seg = idx & 3;
            uint4 val = make_uint4(0, 0, 0, 0);
            if (row < T_)
                val = *(const uint4*)(tq + (size_t)row * E_ + k0 + seg * 8);
            *(uint4*)(sB + row * SPITCH + seg * 16) = val;
        }
        __syncthreads();

        if (ntW > 0) {
            #pragma unroll
            for (int ks = 0; ks < 2; ks++) {
                const uint32_t kloc = ks * 16;

                uint32_t af[4][4];
                #pragma unroll
                for (int mt = 0; mt < 4; mt++) {
                    const uint32_t addr = sAu
                        + (warpM0 + mt * 16 + a_row) * SPITCH + (kloc + a_col) * 2;
                    asm volatile(
                        "ldmatrix.sync.aligned.m8n8.x4.shared.b16 {%0,%1,%2,%3}, [%4];"
                        : "=r"(af[mt][0]), "=r"(af[mt][1]),
                          "=r"(af[mt][2]), "=r"(af[mt][3])
                        : "r"(addr));
                }
                uint32_t bfr[5][2];
                #pragma unroll
                for (int nt = 0; nt < 5; nt++) {
                    if (nt < ntW) {
                        const uint32_t addr = sBu
                            + (warpN0 + nt * 8 + b_row) * SPITCH + (kloc + b_col) * 2;
                        asm volatile(
                            "ldmatrix.sync.aligned.m8n8.x2.shared.b16 {%0,%1}, [%2];"
                            : "=r"(bfr[nt][0]), "=r"(bfr[nt][1])
                            : "r"(addr));
                    }
                }
                #pragma unroll
                for (int nt = 0; nt < 5; nt++) {
                    if (nt < ntW) {
                        #pragma unroll
                        for (int mt = 0; mt < 4; mt++)
                            mma_16816(acc[mt][nt], af[mt], bfr[nt]);
                    }
                }
            }
        }
    }

    // ---- Epilogue ----
    // Row max over computed (c < len) columns only; 0-clamp applied at combine.
    #pragma unroll
    for (int mt = 0; mt < 4; mt++) {
        #pragma unroll
        for (int h = 0; h < 2; h++) {
            float m = -CUDART_INF_F;
            #pragma unroll
            for (int nt = 0; nt < 5; nt++) {
                if (nt < ntW) {
                    #pragma unroll
                    for (int j = 0; j < 2; j++) {
                        const int c = warpN0 + nt * 8 + lanem * 2 + j;
                        if (c < len)
                            m = fmaxf(m, acc[mt][nt][h * 2 + j]);
                    }
                }
            }
            m = fmaxf(m, __shfl_xor_sync(0xffffffffu, m, 1));
            m = fmaxf(m, __shfl_xor_sync(0xffffffffu, m, 2));
            if (lanem == 0)
                rowmax2[warpM0 + mt * 16 + lane4 + 8 * h][wid & 1] = m;
        }
    }

    // Col max over valid rows, only for computed tiles
    #pragma unroll
    for (int nt = 0; nt < 5; nt++) {
        if (nt < ntW) {
            #pragma unroll
            for (int j = 0; j < 2; j++) {
                float m = -CUDART_INF_F;
                #pragma unroll
                for (int mt = 0; mt < 4; mt++) {
                    #pragma unroll
                    for (int h = 0; h < 2; h++) {
                        const int r = warpM0 + mt * 16 + lane4 + 8 * h;
                        const float s = acc[mt][nt][h * 2 + j];
                        m = fmaxf(m, (r < V_) ? s : -CUDART_INF_F);
                    }
                }
                m = fmaxf(m, __shfl_xor_sync(0xffffffffu, m, 4));
                m = fmaxf(m, __shfl_xor_sync(0xffffffffu, m, 8));
                m = fmaxf(m, __shfl_xor_sync(0xffffffffu, m, 16));
                if (lane < 4) {
                    const int c = warpN0 + nt * 8 + lane * 2 + j;
                    colmax2[c][wid >> 1] = m;
                }
            }
        }
    }
    __syncthreads();

    // v2t: per valid row, max of the two N-halves, 0-clamped if any masked col
    {
        float s = 0.f;
        if (tid < V_) {
            s = fmaxf(rowmax2[tid][0], rowmax2[tid][1]);
            if (len < T_) s = fmaxf(s, 0.0f);
        }
        #pragma unroll
        for (int off = 16; off; off >>= 1)
            s += __shfl_xor_sync(0xffffffffu, s, off);
        if (lane == 0) warpsum[wid] = s;
    }
    // t2v partials
    if (wid < 3) {
        const int c = wid * 32 + lane;
        float s = 0.f;
        if (c < len) {
            const float m01 = fmaxf(colmax2[c][0], colmax2[c][1]);
            const float m23 = fmaxf(colmax2[c][2], colmax2[c][3]);
            s = fmaxf(m01, m23);
        }
        #pragma unroll
        for (int off = 16; off; off >>= 1)
            s += __shfl_xor_sync(0xffffffffu, s, off);
        if (lane == 0) t2vpart[wid] = s;
    }
    __syncthreads();

    if (tid == 0) {
        float s1 = 0.f;
        #pragma unroll
        for (int t = 0; t < 8; t++) s1 += warpsum[t];
        out_v2t[b * Q_ + q] = s1 / (float)V_;
        out_t2v[b * Q_ + q] = (t2vpart[0] + t2vpart[1] + t2vpart[2]) / (float)len;
    }
}

// ===========================================================================
// kernel_launch
// ===========================================================================
extern "C" void kernel_launch(void* const* d_in, const int* in_sizes, int n_in,
                              void* d_out, int out_size)
{
    const float* visual_cls     = (const float*)d_in[0];
    const float* visual_tokens  = (const float*)d_in[1];
    const float* textual_cls    = (const float*)d_in[2];
    const float* textual_tokens = (const float*)d_in[3];
    const float* Wv_cls = (const float*)d_in[4];
    const float* bv_cls = (const float*)d_in[5];
    const float* Wt_cls = (const float*)d_in[6];
    const float* bt_cls = (const float*)d_in[7];
    const float* Wv_tok = (const float*)d_in[8];
    const float* bv_tok = (const float*)d_in[9];
    const float* Wt_tok = (const float*)d_in[10];
    const float* bt_tok = (const float*)d_in[11];
    const int*   tlen   = (const int*)d_in[12];

    float* out    = (float*)d_out;
    float* o_vcls = out;
    float* o_tcls = out + 96 * 512;
    float* o_t2v  = out + 2 * 96 * 512;
    float* o_v2t  = o_t2v + 96 * 96;

    float* vtok = nullptr;
    float* ttok = nullptr;
    __nv_bfloat16 *vtok_bf = nullptr, *ttok_bf = nullptr;
    __nv_bfloat16 *wv_bf = nullptr, *wt_bf = nullptr;
    cudaGetSymbolAddress((void**)&vtok, g_vtok);
    cudaGetSymbolAddress((void**)&ttok, g_ttok);
    cudaGetSymbolAddress((void**)&vtok_bf, g_vtok_bf);
    cudaGetSymbolAddress((void**)&ttok_bf, g_ttok_bf);
    cudaGetSymbolAddress((void**)&wv_bf, g_wv_bf);
    cudaGetSymbolAddress((void**)&wt_bf, g_wt_bf);

    // 0. token weights -> bf16
    {
        const int n4 = E_ * DK / 4;
        f32_to_bf16_kernel<<<(n4 + 255) / 256, 256>>>(Wv_tok, wv_bf, n4);
        f32_to_bf16_kernel<<<(n4 + 255) / 256, 256>>>(Wt_tok, wt_bf, n4);
    }
    // 1. cls projections (merged, exact fp32) -> output
    {
        dim3 grid(2, E_ / 64, 2);
        gemm_cls_kernel<<<grid, 256>>>(visual_cls,  Wv_cls, bv_cls, o_vcls,
                                       textual_cls, Wt_cls, bt_cls, o_tcls);
    }
    // 2. token projections -> fp32 scratch (bf16 tensor-core GEMM)
    {
        dim3 gv((VROWS + 127) / 128, E_ / 128);
        gemm_bf16_kernel<<<gv, 256>>>(visual_tokens, wv_bf, bv_tok, vtok, VROWS);
        dim3 gt((TROWS + 127) / 128, E_ / 128);
        gemm_bf16_kernel<<<gt, 256>>>(textual_tokens, wt_bf, bt_tok, ttok, TROWS);
    }
    // 3. L2 normalize -> bf16 scratch
    l2norm_bf16_kernel<<<(VROWS + 7) / 8, 256>>>(vtok, vtok_bf, VROWS);
    l2norm_bf16_kernel<<<(TROWS + 7) / 8, 256>>>(ttok, ttok_bf, TROWS);

    // 4. mma.sync fused similarity + reductions (len-skipped)
    {
        dim3 grid(Q_, B_);
        sim_mma_kernel<<<grid, 256>>>(vtok_bf, ttok_bf, tlen, o_t2v, o_v2t);
    }
}

// round 16
// speedup vs baseline: 11.2144x; 1.2166x over previous
#include <cuda_runtime.h>
#include <cuda_bf16.h>
#include <cstdint>
#include <math_constants.h>

// ---------------------------------------------------------------------------
// Problem constants
// ---------------------------------------------------------------------------
#define B_  96
#define Q_  96
#define V_  197
#define T_  77
#define DK  768
#define E_  512

#define VROWS (B_ * V_)   // 18912
#define TROWS (Q_ * T_)   // 7392

// Scratch (alloc-free: __device__ globals)
__device__ float g_vtok[VROWS * E_];
__device__ float g_ttok[TROWS * E_];
__device__ __align__(16) __nv_bfloat16 g_vtok_bf[VROWS * E_];
__device__ __align__(16) __nv_bfloat16 g_ttok_bf[TROWS * E_];
__device__ __align__(16) __nv_bfloat16 g_wv_bf[E_ * DK];
__device__ __align__(16) __nv_bfloat16 g_wt_bf[E_ * DK];

__device__ __forceinline__ uint32_t smem_u32(const void* p) {
    uint32_t a;
    asm("{ .reg .u64 t; cvta.to.shared.u64 t, %1; cvt.u32.u64 %0, t; }"
        : "=r"(a) : "l"(p));
    return a;
}

__device__ __forceinline__ void mma_16816(float* c, const uint32_t* a,
                                          const uint32_t* b) {
    asm volatile(
        "mma.sync.aligned.m16n8k16.row.col.f32.bf16.bf16.f32 "
        "{%0,%1,%2,%3}, {%4,%5,%6,%7}, {%8,%9}, {%0,%1,%2,%3};"
        : "+f"(c[0]), "+f"(c[1]), "+f"(c[2]), "+f"(c[3])
        : "r"(a[0]), "r"(a[1]), "r"(a[2]), "r"(a[3]), "r"(b[0]), "r"(b[1]));
}

__device__ __forceinline__ void cp_async16(uint32_t dst, const void* src,
                                           uint32_t src_bytes) {
    asm volatile("cp.async.cg.shared.global [%0], [%1], 16, %2;"
                 :: "r"(dst), "l"(src), "r"(src_bytes));
}
#define CP_COMMIT() asm volatile("cp.async.commit_group;" ::: "memory")
#define CP_WAIT(n)  asm volatile("cp.async.wait_group %0;" :: "n"(n) : "memory")

// ===========================================================================
// Weight conversion: both token weight matrices in one launch.
// ===========================================================================
#define WN4 (E_ * DK / 4)   // 98304 float4 per matrix

__global__ __launch_bounds__(256) void weights_to_bf16_kernel(
    const float* __restrict__ w0, const float* __restrict__ w1,
    __nv_bfloat16* __restrict__ d0, __nv_bfloat16* __restrict__ d1)
{
    const int i = blockIdx.x * 256 + threadIdx.x;
    const float* src; __nv_bfloat16* dst; int j;
    if (i < WN4) { src = w0; dst = d0; j = i; }
    else if (i < 2 * WN4) { src = w1; dst = d1; j = i - WN4; }
    else return;
    const float4 f = ((const float4*)src)[j];
    ((__nv_bfloat162*)dst)[j * 2 + 0] = __floats2bfloat162_rn(f.x, f.y);
    ((__nv_bfloat162*)dst)[j * 2 + 1] = __floats2bfloat162_rn(f.z, f.w);
}

// ===========================================================================
// Merged cls projections (exact fp32), register-prefetch pipelined.
// ===========================================================================
__global__ __launch_bounds__(256) void gemm_cls_kernel(
    const float* __restrict__ X0, const float* __restrict__ W0,
    const float* __restrict__ bias0, float* __restrict__ Y0,
    const float* __restrict__ X1, const float* __restrict__ W1,
    const float* __restrict__ bias1, float* __restrict__ Y1)
{
    const float* X    = blockIdx.z ? X1 : X0;
    const float* W    = blockIdx.z ? W1 : W0;
    const float* bias = blockIdx.z ? bias1 : bias0;
    float*       Y    = blockIdx.z ? Y1 : Y0;
    const int M = 96;

    __shared__ __align__(16) float As[16][68];
    __shared__ __align__(16) float Bs[16][68];

    const int tid = threadIdx.x;
    const int tx  = tid & 15;
    const int ty  = tid >> 4;
    const int m0  = blockIdx.x * 64;
    const int n0  = blockIdx.y * 64;

    float acc[4][4] = {};

    const int lrow = tid >> 2;
    const int lkq  = (tid & 3) << 2;
    const int gr   = m0 + lrow;

    float4 pa = make_float4(0.f, 0.f, 0.f, 0.f);
    if (gr < M) pa = *(const float4*)(X + (size_t)gr * DK + lkq);
    float4 pb = *(const float4*)(W + (size_t)(n0 + lrow) * DK + lkq);

    for (int k0 = 0; k0 < DK; k0 += 16) {
        As[lkq + 0][lrow] = pa.x; As[lkq + 1][lrow] = pa.y;
        As[lkq + 2][lrow] = pa.z; As[lkq + 3][lrow] = pa.w;
        Bs[lkq + 0][lrow] = pb.x; Bs[lkq + 1][lrow] = pb.y;
        Bs[lkq + 2][lrow] = pb.z; Bs[lkq + 3][lrow] = pb.w;
        __syncthreads();

        if (k0 + 16 < DK) {
            pa = make_float4(0.f, 0.f, 0.f, 0.f);
            if (gr < M) pa = *(const float4*)(X + (size_t)gr * DK + k0 + 16 + lkq);
            pb = *(const float4*)(W + (size_t)(n0 + lrow) * DK + k0 + 16 + lkq);
        }

        #pragma unroll
        for (int k = 0; k < 16; k++) {
            const float4 a4 = *(const float4*)&As[k][ty * 4];
            const float4 b4 = *(const float4*)&Bs[k][tx * 4];
            const float a[4] = {a4.x, a4.y, a4.z, a4.w};
            const float b[4] = {b4.x, b4.y, b4.z, b4.w};
            #pragma unroll
            for (int i = 0; i < 4; i++)
                #pragma unroll
                for (int j = 0; j < 4; j++)
                    acc[i][j] = fmaf(a[i], b[j], acc[i][j]);
        }
        __syncthreads();
    }

    #pragma unroll
    for (int i = 0; i < 4; i++) {
        const int r = m0 + ty * 4 + i;
        if (r < M) {
            #pragma unroll
            for (int j = 0; j < 4; j++) {
                const int c = n0 + tx * 4 + j;
                Y[(size_t)r * E_ + c] = acc[i][j] + bias[c];
            }
        }
    }
}

// ===========================================================================
// bf16 mma.sync GEMM for token projections, register-prefetch pipelined.
// ===========================================================================
#define GP 80

__global__ __launch_bounds__(256, 2) void gemm_bf16_kernel(
    const float* __restrict__ X, const __nv_bfloat16* __restrict__ Wbf,
    const float* __restrict__ bias, float* __restrict__ Y, int M)
{
    __shared__ __align__(16) char sA[128 * GP];
    __shared__ __align__(16) char sB[128 * GP];

    const int tid  = threadIdx.x;
    const int wid  = tid >> 5;
    const int lane = tid & 31;
    const int m0 = blockIdx.x * 128;
    const int n0 = blockIdx.y * 128;

    const int warpM0 = (wid >> 1) * 32;
    const int warpN0 = (wid & 1) * 64;

    const uint32_t sAu = smem_u32(sA);
    const uint32_t sBu = smem_u32(sB);

    const int rowA[2] = { tid >> 2, (tid + 256) >> 2 };
    const int segA[2] = { tid & 3, (tid + 256) & 3 };

    float acc[2][8][4];
    #pragma unroll
    for (int mt = 0; mt < 2; mt++)
        #pragma unroll
        for (int nt = 0; nt < 8; nt++)
            #pragma unroll
            for (int r = 0; r < 4; r++) acc[mt][nt][r] = 0.f;

    const uint32_t a_row  = (uint32_t)(lane & 15);
    const uint32_t a_col  = (uint32_t)((lane >> 4) << 3);
    const uint32_t bw_row = (uint32_t)((lane & 7) | ((lane >> 4) << 3));
    const uint32_t bw_col = (uint32_t)(((lane >> 3) & 1) << 3);

    uint4 pA[2], pB[2];

    #pragma unroll
    for (int t = 0; t < 2; t++) {
        const int gr = m0 + rowA[t];
        uint4 val = make_uint4(0, 0, 0, 0);
        if (gr < M) {
            const float4 f0 = *(const float4*)(X + (size_t)gr * DK + segA[t] * 8);
            const float4 f1 = *(const float4*)(X + (size_t)gr * DK + segA[t] * 8 + 4);
            __nv_bfloat162 h0 = __floats2bfloat162_rn(f0.x, f0.y);
            __nv_bfloat162 h1 = __floats2bfloat162_rn(f0.z, f0.w);
            __nv_bfloat162 h2 = __floats2bfloat162_rn(f1.x, f1.y);
            __nv_bfloat162 h3 = __floats2bfloat162_rn(f1.z, f1.w);
            val.x = *(uint32_t*)&h0; val.y = *(uint32_t*)&h1;
            val.z = *(uint32_t*)&h2; val.w = *(uint32_t*)&h3;
        }
        pA[t] = val;
        pB[t] = *(const uint4*)(Wbf + (size_t)(n0 + rowA[t]) * DK + segA[t] * 8);
    }

    for (int k0 = 0; k0 < DK; k0 += 32) {
        #pragma unroll
        for (int t = 0; t < 2; t++) {
            *(uint4*)(sA + rowA[t] * GP + segA[t] * 16) = pA[t];
            *(uint4*)(sB + rowA[t] * GP + segA[t] * 16) = pB[t];
        }
        __syncthreads();

        if (k0 + 32 < DK) {
            const int kn = k0 + 32;
            #pragma unroll
            for (int t = 0; t < 2; t++) {
                const int gr = m0 + rowA[t];
                uint4 val = make_uint4(0, 0, 0, 0);
                if (gr < M) {
                    const float4 f0 = *(const float4*)(X + (size_t)gr * DK + kn + segA[t] * 8);
                    const float4 f1 = *(const float4*)(X + (size_t)gr * DK + kn + segA[t] * 8 + 4);
                    __nv_bfloat162 h0 = __floats2bfloat162_rn(f0.x, f0.y);
                    __nv_bfloat162 h1 = __floats2bfloat162_rn(f0.z, f0.w);
                    __nv_bfloat162 h2 = __floats2bfloat162_rn(f1.x, f1.y);
                    __nv_bfloat162 h3 = __floats2bfloat162_rn(f1.z, f1.w);
                    val.x = *(uint32_t*)&h0; val.y = *(uint32_t*)&h1;
                    val.z = *(uint32_t*)&h2; val.w = *(uint32_t*)&h3;
                }
                pA[t] = val;
                pB[t] = *(const uint4*)(Wbf + (size_t)(n0 + rowA[t]) * DK + kn + segA[t] * 8);
            }
        }

        #pragma unroll
        for (int ks = 0; ks < 2; ks++) {
            const uint32_t kloc = ks * 16;

            uint32_t af[2][4];
            #pragma unroll
            for (int mt = 0; mt < 2; mt++) {
                const uint32_t addr = sAu
                    + (warpM0 + mt * 16 + a_row) * GP + (kloc + a_col) * 2;
                asm volatile(
                    "ldmatrix.sync.aligned.m8n8.x4.shared.b16 {%0,%1,%2,%3}, [%4];"
                    : "=r"(af[mt][0]), "=r"(af[mt][1]),
                      "=r"(af[mt][2]), "=r"(af[mt][3])
                    : "r"(addr));
            }
            uint32_t bfr[4][4];
            #pragma unroll
            for (int nt2 = 0; nt2 < 4; nt2++) {
                const uint32_t addr = sBu
                    + (warpN0 + nt2 * 16 + bw_row) * GP + (kloc + bw_col) * 2;
                asm volatile(
                    "ldmatrix.sync.aligned.m8n8.x4.shared.b16 {%0,%1,%2,%3}, [%4];"
                    : "=r"(bfr[nt2][0]), "=r"(bfr[nt2][1]),
                      "=r"(bfr[nt2][2]), "=r"(bfr[nt2][3])
                    : "r"(addr));
            }
            #pragma unroll
            for (int mt = 0; mt < 2; mt++)
                #pragma unroll
                for (int nt2 = 0; nt2 < 4; nt2++) {
                    mma_16816(acc[mt][nt2 * 2 + 0], af[mt], &bfr[nt2][0]);
                    mma_16816(acc[mt][nt2 * 2 + 1], af[mt], &bfr[nt2][2]);
                }
        }
        __syncthreads();
    }

    const int lane4 = lane >> 2;
    const int lanem = lane & 3;
    #pragma unroll
    for (int mt = 0; mt < 2; mt++) {
        #pragma unroll
        for (int h = 0; h < 2; h++) {
            const int r = m0 + warpM0 + mt * 16 + lane4 + 8 * h;
            if (r < M) {
                #pragma unroll
                for (int nt = 0; nt < 8; nt++) {
                    const int c = n0 + warpN0 + nt * 8 + lanem * 2;
                    float2 o;
                    o.x = acc[mt][nt][h * 2 + 0] + bias[c];
                    o.y = acc[mt][nt][h * 2 + 1] + bias[c + 1];
                    *(float2*)(Y + (size_t)r * E_ + c) = o;
                }
            }
        }
    }
}

// ===========================================================================
// L2 normalization (both token sets in one launch): fp32 in -> bf16 out.
// Rows [0, VROWS) -> vtok, rows [VROWS, VROWS+TROWS) -> ttok.
// ===========================================================================
__global__ __launch_bounds__(256) void l2norm_bf16_kernel(
    const float* __restrict__ Yv, __nv_bfloat16* __restrict__ Ov,
    const float* __restrict__ Yt, __nv_bfloat16* __restrict__ Ot)
{
    int row = blockIdx.x * 8 + (threadIdx.x >> 5);
    const int lane = threadIdx.x & 31;
    const float* Y; __nv_bfloat16* O;
    if (row < VROWS) { Y = Yv; O = Ov; }
    else if (row < VROWS + TROWS) { Y = Yt; O = Ot; row -= VROWS; }
    else return;

    const float4* p = (const float4*)(Y + (size_t)row * E_);
    float4 v[4];
    float ss = 0.f;
    #pragma unroll
    for (int t = 0; t < 4; t++) {
        v[t] = p[lane + 32 * t];
        ss += v[t].x * v[t].x + v[t].y * v[t].y + v[t].z * v[t].z + v[t].w * v[t].w;
    }
    #pragma unroll
    for (int off = 16; off; off >>= 1)
        ss += __shfl_xor_sync(0xffffffffu, ss, off);

    const float inv = 1.f / fmaxf(sqrtf(ss), 1e-12f);

    __nv_bfloat162* o2 = (__nv_bfloat162*)(O + (size_t)row * E_);
    #pragma unroll
    for (int t = 0; t < 4; t++) {
        const int e = lane + 32 * t;
        o2[e * 2 + 0] = __floats2bfloat162_rn(v[t].x * inv, v[t].y * inv);
        o2[e * 2 + 1] = __floats2bfloat162_rn(v[t].z * inv, v[t].w * inv);
    }
}

// ===========================================================================
// mma.sync bf16 fused similarity kernel: len-skip + 2-stage cp.async pipeline.
// One CTA per (b, q).
// ===========================================================================
#define SPITCH 80
#define ASTG   (256 * SPITCH)   // 20480
#define BSTG   (80 * SPITCH)    // 6400
#define NCH    16               // K chunks of 32

__global__ __launch_bounds__(256, 2) void sim_mma_kernel(
    const __nv_bfloat16* __restrict__ vtok, const __nv_bfloat16* __restrict__ ttok,
    const int* __restrict__ tlen,
    float* __restrict__ out_t2v, float* __restrict__ out_v2t)
{
    __shared__ __align__(16) char sA[2 * ASTG];
    __shared__ __align__(16) char sB[2 * BSTG];
    __shared__ float rowmax2[256][2];
    __shared__ float colmax2[80][4];
    __shared__ float warpsum[8];
    __shared__ float t2vpart[3];

    const int tid  = threadIdx.x;
    const int wid  = tid >> 5;
    const int lane = tid & 31;
    const int q = blockIdx.x;
    const int b = blockIdx.y;

    const int warpM0 = (wid >> 1) * 64;
    const int warpN0 = (wid & 1) * 40;
    const int lane4  = lane >> 2;
    const int lanem  = lane & 3;

    const int len  = tlen[q];
    const int dlen = len - warpN0;
    const int ntW  = (dlen <= 0) ? 0 : (dlen >= 40 ? 5 : ((dlen + 7) >> 3));

    const uint32_t sAu = smem_u32(sA);
    const uint32_t sBu = smem_u32(sB);

    const __nv_bfloat16* vb = vtok + (size_t)b * V_ * E_;
    const __nv_bfloat16* tq = ttok + (size_t)q * T_ * E_;

    const int rb  = tid >> 2;    // 0..63
    const int seg = tid & 3;     // 0..3

    float acc[4][5][4];
    #pragma unroll
    for (int mt = 0; mt < 4; mt++)
        #pragma unroll
        for (int nt = 0; nt < 5; nt++)
            #pragma unroll
            for (int r = 0; r < 4; r++) acc[mt][nt][r] = 0.f;

    const uint32_t a_row = (uint32_t)(lane & 15);
    const uint32_t a_col = (uint32_t)((lane >> 4) << 3);
    const uint32_t b_row = (uint32_t)(lane & 7);
    const uint32_t b_col = (uint32_t)(((lane >> 3) & 1) << 3);

    // --- cp.async chunk issue: A 4 slots + B 1-2 slots per thread ---
    auto issue_chunk = [&](int ch) {
        const int s = ch & 1;
        const uint32_t a0 = sAu + s * ASTG;
        const uint32_t b0 = sBu + s * BSTG;
        const int koff = ch * 32 + seg * 8;
        #pragma unroll
        for (int t = 0; t < 4; t++) {
            const int row = rb + 64 * t;
            const int rc  = (row < V_) ? row : 0;
            cp_async16(a0 + row * SPITCH + seg * 16,
                       vb + (size_t)rc * E_ + koff,
                       (row < V_) ? 16u : 0u);
        }
        cp_async16(b0 + rb * SPITCH + seg * 16,
                   tq + (size_t)rb * E_ + koff, 16u);   // rows 0..63 always valid
        if (tid < 64) {
            const int row = 64 + rb;                    // rows 64..79
            const int rc  = (row < T_) ? row : 0;
            cp_async16(b0 + row * SPITCH + seg * 16,
                       tq + (size_t)rc * E_ + koff,
                       (row < T_) ? 16u : 0u);
        }
        CP_COMMIT();
    };

    issue_chunk(0);

    for (int ch = 0; ch < NCH; ch++) {
        if (ch + 1 < NCH) {
            issue_chunk(ch + 1);
            CP_WAIT(1);
        } else {
            CP_WAIT(0);
        }
        __syncthreads();

        const uint32_t aBase = sAu + (ch & 1) * ASTG;
        const uint32_t bBase = sBu + (ch & 1) * BSTG;

        if (ntW > 0) {
            #pragma unroll
            for (int ks = 0; ks < 2; ks++) {
                const uint32_t kloc = ks * 16;

                uint32_t af[4][4];
                #pragma unroll
                for (int mt = 0; mt < 4; mt++) {
                    const uint32_t addr = aBase
                        + (warpM0 + mt * 16 + a_row) * SPITCH + (kloc + a_col) * 2;
                    asm volatile(
                        "ldmatrix.sync.aligned.m8n8.x4.shared.b16 {%0,%1,%2,%3}, [%4];"
                        : "=r"(af[mt][0]), "=r"(af[mt][1]),
                          "=r"(af[mt][2]), "=r"(af[mt][3])
                        : "r"(addr));
                }
                uint32_t bfr[5][2];
                #pragma unroll
                for (int nt = 0; nt < 5; nt++) {
                    if (nt < ntW) {
                        const uint32_t addr = bBase
                            + (warpN0 + nt * 8 + b_row) * SPITCH + (kloc + b_col) * 2;
                        asm volatile(
                            "ldmatrix.sync.aligned.m8n8.x2.shared.b16 {%0,%1}, [%2];"
                            : "=r"(bfr[nt][0]), "=r"(bfr[nt][1])
                            : "r"(addr));
                    }
                }
                #pragma unroll
                for (int nt = 0; nt < 5; nt++) {
                    if (nt < ntW) {
                        #pragma unroll
                        for (int mt = 0; mt < 4; mt++)
                            mma_16816(acc[mt][nt], af[mt], bfr[nt]);
                    }
                }
            }
        }
        __syncthreads();
    }

    // ---- Epilogue (unchanged, len-skipped) ----
    #pragma unroll
    for (int mt = 0; mt < 4; mt++) {
        #pragma unroll
        for (int h = 0; h < 2; h++) {
            float m = -CUDART_INF_F;
            #pragma unroll
            for (int nt = 0; nt < 5; nt++) {
                if (nt < ntW) {
                    #pragma unroll
                    for (int j = 0; j < 2; j++) {
                        const int c = warpN0 + nt * 8 + lanem * 2 + j;
                        if (c < len)
                            m = fmaxf(m, acc[mt][nt][h * 2 + j]);
                    }
                }
            }
            m = fmaxf(m, __shfl_xor_sync(0xffffffffu, m, 1));
            m = fmaxf(m, __shfl_xor_sync(0xffffffffu, m, 2));
            if (lanem == 0)
                rowmax2[warpM0 + mt * 16 + lane4 + 8 * h][wid & 1] = m;
        }
    }

    #pragma unroll
    for (int nt = 0; nt < 5; nt++) {
        if (nt < ntW) {
            #pragma unroll
            for (int j = 0; j < 2; j++) {
                float m = -CUDART_INF_F;
                #pragma unroll
                for (int mt = 0; mt < 4; mt++) {
                    #pragma unroll
                    for (int h = 0; h < 2; h++) {
                        const int r = warpM0 + mt * 16 + lane4 + 8 * h;
                        const float s = acc[mt][nt][h * 2 + j];
                        m = fmaxf(m, (r < V_) ? s : -CUDART_INF_F);
                    }
                }
                m = fmaxf(m, __shfl_xor_sync(0xffffffffu, m, 4));
                m = fmaxf(m, __shfl_xor_sync(0xffffffffu, m, 8));
                m = fmaxf(m, __shfl_xor_sync(0xffffffffu, m, 16));
                if (lane < 4) {
                    const int c = warpN0 + nt * 8 + lane * 2 + j;
                    colmax2[c][wid >> 1] = m;
                }
            }
        }
    }
    __syncthreads();

    {
        float s = 0.f;
        if (tid < V_) {
            s = fmaxf(rowmax2[tid][0], rowmax2[tid][1]);
            if (len < T_) s = fmaxf(s, 0.0f);
        }
        #pragma unroll
        for (int off = 16; off; off >>= 1)
            s += __shfl_xor_sync(0xffffffffu, s, off);
        if (lane == 0) warpsum[wid] = s;
    }
    if (wid < 3) {
        const int c = wid * 32 + lane;
        float s = 0.f;
        if (c < len) {
            const float m01 = fmaxf(colmax2[c][0], colmax2[c][1]);
            const float m23 = fmaxf(colmax2[c][2], colmax2[c][3]);
            s = fmaxf(m01, m23);
        }
        #pragma unroll
        for (int off = 16; off; off >>= 1)
            s += __shfl_xor_sync(0xffffffffu, s, off);
        if (lane == 0) t2vpart[wid] = s;
    }
    __syncthreads();

    if (tid == 0) {
        float s1 = 0.f;
        #pragma unroll
        for (int t = 0; t < 8; t++) s1 += warpsum[t];
        out_v2t[b * Q_ + q] = s1 / (float)V_;
        out_t2v[b * Q_ + q] = (t2vpart[0] + t2vpart[1] + t2vpart[2]) / (float)len;
    }
}

// ===========================================================================
// kernel_launch
// ===========================================================================
extern "C" void kernel_launch(void* const* d_in, const int* in_sizes, int n_in,
                              void* d_out, int out_size)
{
    const float* visual_cls     = (const float*)d_in[0];
    const float* visual_tokens  = (const float*)d_in[1];
    const float* textual_cls    = (const float*)d_in[2];
    const float* textual_tokens = (const float*)d_in[3];
    const float* Wv_cls = (const float*)d_in[4];
    const float* bv_cls = (const float*)d_in[5];
    const float* Wt_cls = (const float*)d_in[6];
    const float* bt_cls = (const float*)d_in[7];
    const float* Wv_tok = (const float*)d_in[8];
    const float* bv_tok = (const float*)d_in[9];
    const float* Wt_tok = (const float*)d_in[10];
    const float* bt_tok = (const float*)d_in[11];
    const int*   tlen   = (const int*)d_in[12];

    float* out    = (float*)d_out;
    float* o_vcls = out;
    float* o_tcls = out + 96 * 512;
    float* o_t2v  = out + 2 * 96 * 512;
    float* o_v2t  = o_t2v + 96 * 96;

    float* vtok = nullptr;
    float* ttok = nullptr;
    __nv_bfloat16 *vtok_bf = nullptr, *ttok_bf = nullptr;
    __nv_bfloat16 *wv_bf = nullptr, *wt_bf = nullptr;
    cudaGetSymbolAddress((void**)&vtok, g_vtok);
    cudaGetSymbolAddress((void**)&ttok, g_ttok);
    cudaGetSymbolAddress((void**)&vtok_bf, g_vtok_bf);
    cudaGetSymbolAddress((void**)&ttok_bf, g_ttok_bf);
    cudaGetSymbolAddress((void**)&wv_bf, g_wv_bf);
    cudaGetSymbolAddress((void**)&wt_bf, g_wt_bf);

    // 0. token weights -> bf16 (single launch)
    weights_to_bf16_kernel<<<(2 * WN4 + 255) / 256, 256>>>(Wv_tok, Wt_tok,
                                                           wv_bf, wt_bf);
    // 1. cls projections (merged, exact fp32) -> output
    {
        dim3 grid(2, E_ / 64, 2);
        gemm_cls_kernel<<<grid, 256>>>(visual_cls,  Wv_cls, bv_cls, o_vcls,
                                       textual_cls, Wt_cls, bt_cls, o_tcls);
    }
    // 2. token projections -> fp32 scratch (bf16 tensor-core GEMM)
    {
        dim3 gv((VROWS + 127) / 128, E_ / 128);
        gemm_bf16_kernel<<<gv, 256>>>(visual_tokens, wv_bf, bv_tok, vtok, VROWS);
        dim3 gt((TROWS + 127) / 128, E_ / 128);
        gemm_bf16_kernel<<<gt, 256>>>(textual_tokens, wt_bf, bt_tok, ttok, TROWS);
    }
    // 3. L2 normalize -> bf16 (single launch for both)
    l2norm_bf16_kernel<<<(VROWS + TROWS + 7) / 8, 256>>>(vtok, vtok_bf,
                                                         ttok, ttok_bf);
    // 4. mma.sync fused similarity + reductions (len-skip + cp.async pipeline)
    {
        dim3 grid(Q_, B_);
        sim_mma_kernel<<<grid, 256>>>(vtok_bf, ttok_bf, tlen, o_t2v, o_v2t);
    }
}

// round 17
// speedup vs baseline: 12.0586x; 1.0753x over previous
#include <cuda_runtime.h>
#include <cuda_bf16.h>
#include <cstdint>
#include <math_constants.h>

// ---------------------------------------------------------------------------
// Problem constants
// ---------------------------------------------------------------------------
#define B_  96
#define Q_  96
#define V_  197
#define T_  77
#define DK  768
#define E_  512

#define VROWS (B_ * V_)   // 18912
#define TROWS (Q_ * T_)   // 7392

// Scratch (alloc-free: __device__ globals)
__device__ float g_vtok[VROWS * E_];
__device__ float g_ttok[TROWS * E_];
__device__ __align__(16) __nv_bfloat16 g_vtok_bf[VROWS * E_];
__device__ __align__(16) __nv_bfloat16 g_ttok_bf[TROWS * E_];
__device__ __align__(16) __nv_bfloat16 g_wv_bf[E_ * DK];
__device__ __align__(16) __nv_bfloat16 g_wt_bf[E_ * DK];

__device__ __forceinline__ uint32_t smem_u32(const void* p) {
    uint32_t a;
    asm("{ .reg .u64 t; cvta.to.shared.u64 t, %1; cvt.u32.u64 %0, t; }"
        : "=r"(a) : "l"(p));
    return a;
}

__device__ __forceinline__ void mma_16816(float* c, const uint32_t* a,
                                          const uint32_t* b) {
    asm volatile(
        "mma.sync.aligned.m16n8k16.row.col.f32.bf16.bf16.f32 "
        "{%0,%1,%2,%3}, {%4,%5,%6,%7}, {%8,%9}, {%0,%1,%2,%3};"
        : "+f"(c[0]), "+f"(c[1]), "+f"(c[2]), "+f"(c[3])
        : "r"(a[0]), "r"(a[1]), "r"(a[2]), "r"(a[3]), "r"(b[0]), "r"(b[1]));
}

__device__ __forceinline__ void cp_async16(uint32_t dst, const void* src,
                                           uint32_t src_bytes) {
    asm volatile("cp.async.cg.shared.global [%0], [%1], 16, %2;"
                 :: "r"(dst), "l"(src), "r"(src_bytes));
}
#define CP_COMMIT() asm volatile("cp.async.commit_group;" ::: "memory")
#define CP_WAIT(n)  asm volatile("cp.async.wait_group %0;" :: "n"(n) : "memory")

// ===========================================================================
// Weight conversion: both token weight matrices in one launch.
// ===========================================================================
#define WN4 (E_ * DK / 4)   // 98304 float4 per matrix

__global__ __launch_bounds__(256) void weights_to_bf16_kernel(
    const float* __restrict__ w0, const float* __restrict__ w1,
    __nv_bfloat16* __restrict__ d0, __nv_bfloat16* __restrict__ d1)
{
    const int i = blockIdx.x * 256 + threadIdx.x;
    const float* src; __nv_bfloat16* dst; int j;
    if (i < WN4) { src = w0; dst = d0; j = i; }
    else if (i < 2 * WN4) { src = w1; dst = d1; j = i - WN4; }
    else return;
    const float4 f = ((const float4*)src)[j];
    ((__nv_bfloat162*)dst)[j * 2 + 0] = __floats2bfloat162_rn(f.x, f.y);
    ((__nv_bfloat162*)dst)[j * 2 + 1] = __floats2bfloat162_rn(f.z, f.w);
}

// ===========================================================================
// Merged cls projections (exact fp32), register-prefetch pipelined.
// ===========================================================================
__global__ __launch_bounds__(256) void gemm_cls_kernel(
    const float* __restrict__ X0, const float* __restrict__ W0,
    const float* __restrict__ bias0, float* __restrict__ Y0,
    const float* __restrict__ X1, const float* __restrict__ W1,
    const float* __restrict__ bias1, float* __restrict__ Y1)
{
    const float* X    = blockIdx.z ? X1 : X0;
    const float* W    = blockIdx.z ? W1 : W0;
    const float* bias = blockIdx.z ? bias1 : bias0;
    float*       Y    = blockIdx.z ? Y1 : Y0;
    const int M = 96;

    __shared__ __align__(16) float As[16][68];
    __shared__ __align__(16) float Bs[16][68];

    const int tid = threadIdx.x;
    const int tx  = tid & 15;
    const int ty  = tid >> 4;
    const int m0  = blockIdx.x * 64;
    const int n0  = blockIdx.y * 64;

    float acc[4][4] = {};

    const int lrow = tid >> 2;
    const int lkq  = (tid & 3) << 2;
    const int gr   = m0 + lrow;

    float4 pa = make_float4(0.f, 0.f, 0.f, 0.f);
    if (gr < M) pa = *(const float4*)(X + (size_t)gr * DK + lkq);
    float4 pb = *(const float4*)(W + (size_t)(n0 + lrow) * DK + lkq);

    for (int k0 = 0; k0 < DK; k0 += 16) {
        As[lkq + 0][lrow] = pa.x; As[lkq + 1][lrow] = pa.y;
        As[lkq + 2][lrow] = pa.z; As[lkq + 3][lrow] = pa.w;
        Bs[lkq + 0][lrow] = pb.x; Bs[lkq + 1][lrow] = pb.y;
        Bs[lkq + 2][lrow] = pb.z; Bs[lkq + 3][lrow] = pb.w;
        __syncthreads();

        if (k0 + 16 < DK) {
            pa = make_float4(0.f, 0.f, 0.f, 0.f);
            if (gr < M) pa = *(const float4*)(X + (size_t)gr * DK + k0 + 16 + lkq);
            pb = *(const float4*)(W + (size_t)(n0 + lrow) * DK + k0 + 16 + lkq);
        }

        #pragma unroll
        for (int k = 0; k < 16; k++) {
            const float4 a4 = *(const float4*)&As[k][ty * 4];
            const float4 b4 = *(const float4*)&Bs[k][tx * 4];
            const float a[4] = {a4.x, a4.y, a4.z, a4.w};
            const float b[4] = {b4.x, b4.y, b4.z, b4.w};
            #pragma unroll
            for (int i = 0; i < 4; i++)
                #pragma unroll
                for (int j = 0; j < 4; j++)
                    acc[i][j] = fmaf(a[i], b[j], acc[i][j]);
        }
        __syncthreads();
    }

    #pragma unroll
    for (int i = 0; i < 4; i++) {
        const int r = m0 + ty * 4 + i;
        if (r < M) {
            #pragma unroll
            for (int j = 0; j < 4; j++) {
                const int c = n0 + tx * 4 + j;
                Y[(size_t)r * E_ + c] = acc[i][j] + bias[c];
            }
        }
    }
}

// ===========================================================================
// bf16 mma.sync GEMM for token projections, register-prefetch pipelined.
// ===========================================================================
#define GP 80

__global__ __launch_bounds__(256, 2) void gemm_bf16_kernel(
    const float* __restrict__ X, const __nv_bfloat16* __restrict__ Wbf,
    const float* __restrict__ bias, float* __restrict__ Y, int M)
{
    __shared__ __align__(16) char sA[128 * GP];
    __shared__ __align__(16) char sB[128 * GP];

    const int tid  = threadIdx.x;
    const int wid  = tid >> 5;
    const int lane = tid & 31;
    const int m0 = blockIdx.x * 128;
    const int n0 = blockIdx.y * 128;

    const int warpM0 = (wid >> 1) * 32;
    const int warpN0 = (wid & 1) * 64;

    const uint32_t sAu = smem_u32(sA);
    const uint32_t sBu = smem_u32(sB);

    const int rowA[2] = { tid >> 2, (tid + 256) >> 2 };
    const int segA[2] = { tid & 3, (tid + 256) & 3 };

    float acc[2][8][4];
    #pragma unroll
    for (int mt = 0; mt < 2; mt++)
        #pragma unroll
        for (int nt = 0; nt < 8; nt++)
            #pragma unroll
            for (int r = 0; r < 4; r++) acc[mt][nt][r] = 0.f;

    const uint32_t a_row  = (uint32_t)(lane & 15);
    const uint32_t a_col  = (uint32_t)((lane >> 4) << 3);
    const uint32_t bw_row = (uint32_t)((lane & 7) | ((lane >> 4) << 3));
    const uint32_t bw_col = (uint32_t)(((lane >> 3) & 1) << 3);

    uint4 pA[2], pB[2];

    #pragma unroll
    for (int t = 0; t < 2; t++) {
        const int gr = m0 + rowA[t];
        uint4 val = make_uint4(0, 0, 0, 0);
        if (gr < M) {
            const float4 f0 = *(const float4*)(X + (size_t)gr * DK + segA[t] * 8);
            const float4 f1 = *(const float4*)(X + (size_t)gr * DK + segA[t] * 8 + 4);
            __nv_bfloat162 h0 = __floats2bfloat162_rn(f0.x, f0.y);
            __nv_bfloat162 h1 = __floats2bfloat162_rn(f0.z, f0.w);
            __nv_bfloat162 h2 = __floats2bfloat162_rn(f1.x, f1.y);
            __nv_bfloat162 h3 = __floats2bfloat162_rn(f1.z, f1.w);
            val.x = *(uint32_t*)&h0; val.y = *(uint32_t*)&h1;
            val.z = *(uint32_t*)&h2; val.w = *(uint32_t*)&h3;
        }
        pA[t] = val;
        pB[t] = *(const uint4*)(Wbf + (size_t)(n0 + rowA[t]) * DK + segA[t] * 8);
    }

    for (int k0 = 0; k0 < DK; k0 += 32) {
        #pragma unroll
        for (int t = 0; t < 2; t++) {
            *(uint4*)(sA + rowA[t] * GP + segA[t] * 16) = pA[t];
            *(uint4*)(sB + rowA[t] * GP + segA[t] * 16) = pB[t];
        }
        __syncthreads();

        if (k0 + 32 < DK) {
            const int kn = k0 + 32;
            #pragma unroll
            for (int t = 0; t < 2; t++) {
                const int gr = m0 + rowA[t];
                uint4 val = make_uint4(0, 0, 0, 0);
                if (gr < M) {
                    const float4 f0 = *(const float4*)(X + (size_t)gr * DK + kn + segA[t] * 8);
                    const float4 f1 = *(const float4*)(X + (size_t)gr * DK + kn + segA[t] * 8 + 4);
                    __nv_bfloat162 h0 = __floats2bfloat162_rn(f0.x, f0.y);
                    __nv_bfloat162 h1 = __floats2bfloat162_rn(f0.z, f0.w);
                    __nv_bfloat162 h2 = __floats2bfloat162_rn(f1.x, f1.y);
                    __nv_bfloat162 h3 = __floats2bfloat162_rn(f1.z, f1.w);
                    val.x = *(uint32_t*)&h0; val.y = *(uint32_t*)&h1;
                    val.z = *(uint32_t*)&h2; val.w = *(uint32_t*)&h3;
                }
                pA[t] = val;
                pB[t] = *(const uint4*)(Wbf + (size_t)(n0 + rowA[t]) * DK + kn + segA[t] * 8);
            }
        }

        #pragma unroll
        for (int ks = 0; ks < 2; ks++) {
            const uint32_t kloc = ks * 16;

            uint32_t af[2][4];
            #pragma unroll
            for (int mt = 0; mt < 2; mt++) {
                const uint32_t addr = sAu
                    + (warpM0 + mt * 16 + a_row) * GP + (kloc + a_col) * 2;
                asm volatile(
                    "ldmatrix.sync.aligned.m8n8.x4.shared.b16 {%0,%1,%2,%3}, [%4];"
                    : "=r"(af[mt][0]), "=r"(af[mt][1]),
                      "=r"(af[mt][2]), "=r"(af[mt][3])
                    : "r"(addr));
            }
            uint32_t bfr[4][4];
            #pragma unroll
            for (int nt2 = 0; nt2 < 4; nt2++) {
                const uint32_t addr = sBu
                    + (warpN0 + nt2 * 16 + bw_row) * GP + (kloc + bw_col) * 2;
                asm volatile(
                    "ldmatrix.sync.aligned.m8n8.x4.shared.b16 {%0,%1,%2,%3}, [%4];"
                    : "=r"(bfr[nt2][0]), "=r"(bfr[nt2][1]),
                      "=r"(bfr[nt2][2]), "=r"(bfr[nt2][3])
                    : "r"(addr));
            }
            #pragma unroll
            for (int mt = 0; mt < 2; mt++)
                #pragma unroll
                for (int nt2 = 0; nt2 < 4; nt2++) {
                    mma_16816(acc[mt][nt2 * 2 + 0], af[mt], &bfr[nt2][0]);
                    mma_16816(acc[mt][nt2 * 2 + 1], af[mt], &bfr[nt2][2]);
                }
        }
        __syncthreads();
    }

    const int lane4 = lane >> 2;
    const int lanem = lane & 3;
    #pragma unroll
    for (int mt = 0; mt < 2; mt++) {
        #pragma unroll
        for (int h = 0; h < 2; h++) {
            const int r = m0 + warpM0 + mt * 16 + lane4 + 8 * h;
            if (r < M) {
                #pragma unroll
                for (int nt = 0; nt < 8; nt++) {
                    const int c = n0 + warpN0 + nt * 8 + lanem * 2;
                    float2 o;
                    o.x = acc[mt][nt][h * 2 + 0] + bias[c];
                    o.y = acc[mt][nt][h * 2 + 1] + bias[c + 1];
                    *(float2*)(Y + (size_t)r * E_ + c) = o;
                }
            }
        }
    }
}

// ===========================================================================
// L2 normalization (both token sets in one launch): fp32 in -> bf16 out.
// ===========================================================================
__global__ __launch_bounds__(256) void l2norm_bf16_kernel(
    const float* __restrict__ Yv, __nv_bfloat16* __restrict__ Ov,
    const float* __restrict__ Yt, __nv_bfloat16* __restrict__ Ot)
{
    int row = blockIdx.x * 8 + (threadIdx.x >> 5);
    const int lane = threadIdx.x & 31;
    const float* Y; __nv_bfloat16* O;
    if (row < VROWS) { Y = Yv; O = Ov; }
    else if (row < VROWS + TROWS) { Y = Yt; O = Ot; row -= VROWS; }
    else return;

    const float4* p = (const float4*)(Y + (size_t)row * E_);
    float4 v[4];
    float ss = 0.f;
    #pragma unroll
    for (int t = 0; t < 4; t++) {
        v[t] = p[lane + 32 * t];
        ss += v[t].x * v[t].x + v[t].y * v[t].y + v[t].z * v[t].z + v[t].w * v[t].w;
    }
    #pragma unroll
    for (int off = 16; off; off >>= 1)
        ss += __shfl_xor_sync(0xffffffffu, ss, off);

    const float inv = 1.f / fmaxf(sqrtf(ss), 1e-12f);

    __nv_bfloat162* o2 = (__nv_bfloat162*)(O + (size_t)row * E_);
    #pragma unroll
    for (int t = 0; t < 4; t++) {
        const int e = lane + 32 * t;
        o2[e * 2 + 0] = __floats2bfloat162_rn(v[t].x * inv, v[t].y * inv);
        o2[e * 2 + 1] = __floats2bfloat162_rn(v[t].z * inv, v[t].w * inv);
    }
}

// ===========================================================================
// sim kernel: len-skip + M trimmed to 208 rows + 3-stage cp.async ring with
// ONE __syncthreads per K-chunk. One CTA per (b, q).
// M-groups (wid>>1): rows {0-47, 48-95, 96-143, 144-207}; tiles {3,3,3,4}.
// ===========================================================================
#define SPITCH 80
#define MPAD   208
#define ASTG   (MPAD * SPITCH)   // 16640
#define BSTG   (80 * SPITCH)     // 6400
#define NST    3
#define NCH    16                // K chunks of 32

__global__ __launch_bounds__(256, 2) void sim_mma_kernel(
    const __nv_bfloat16* __restrict__ vtok, const __nv_bfloat16* __restrict__ ttok,
    const int* __restrict__ tlen,
    float* __restrict__ out_t2v, float* __restrict__ out_v2t)
{
    __shared__ __align__(16) char sA[NST * ASTG];
    __shared__ __align__(16) char sB[NST * BSTG];
    __shared__ float rowmax2[MPAD][2];
    __shared__ float colmax2[80][4];
    __shared__ float warpsum[8];
    __shared__ float t2vpart[3];

    const int tid  = threadIdx.x;
    const int wid  = tid >> 5;
    const int lane = tid & 31;
    const int q = blockIdx.x;
    const int b = blockIdx.y;

    const int g      = wid >> 1;            // M group 0..3
    const int mbase  = g * 48;              // 0,48,96,144
    const int ntM    = (g == 3) ? 4 : 3;    // m16 tiles in this group
    const int warpN0 = (wid & 1) * 40;
    const int lane4  = lane >> 2;
    const int lanem  = lane & 3;

    const int len  = tlen[q];
    const int dlen = len - warpN0;
    const int ntW  = (dlen <= 0) ? 0 : (dlen >= 40 ? 5 : ((dlen + 7) >> 3));

    const uint32_t sAu = smem_u32(sA);
    const uint32_t sBu = smem_u32(sB);

    const __nv_bfloat16* vb = vtok + (size_t)b * V_ * E_;
    const __nv_bfloat16* tq = ttok + (size_t)q * T_ * E_;

    const int rb  = tid >> 2;    // 0..63
    const int seg = tid & 3;     // 0..3

    float acc[4][5][4];
    #pragma unroll
    for (int mt = 0; mt < 4; mt++)
        #pragma unroll
        for (int nt = 0; nt < 5; nt++)
            #pragma unroll
            for (int r = 0; r < 4; r++) acc[mt][nt][r] = 0.f;

    const uint32_t a_row = (uint32_t)(lane & 15);
    const uint32_t a_col = (uint32_t)((lane >> 4) << 3);
    const uint32_t b_row = (uint32_t)(lane & 7);
    const uint32_t b_col = (uint32_t)(((lane >> 3) & 1) << 3);

    auto issue_chunk = [&](int ch) {
        const int s = ch % NST;
        const uint32_t a0 = sAu + s * ASTG;
        const uint32_t b0 = sBu + s * BSTG;
        const int koff = ch * 32 + seg * 8;
        #pragma unroll
        for (int t = 0; t < 4; t++) {
            const int row = rb + 64 * t;
            if (row < MPAD) {
                const int rc = (row < V_) ? row : 0;
                cp_async16(a0 + row * SPITCH + seg * 16,
                           vb + (size_t)rc * E_ + koff,
                           (row < V_) ? 16u : 0u);
            }
        }
        cp_async16(b0 + rb * SPITCH + seg * 16,
                   tq + (size_t)rb * E_ + koff, 16u);   // rows 0..63 valid
        if (tid < 64) {
            const int row = 64 + rb;                    // rows 64..79
            const int rc  = (row < T_) ? row : 0;
            cp_async16(b0 + row * SPITCH + seg * 16,
                       tq + (size_t)rc * E_ + koff,
                       (row < T_) ? 16u : 0u);
        }
        CP_COMMIT();
    };

    issue_chunk(0);
    issue_chunk(1);

    for (int ch = 0; ch < NCH; ch++) {
        if (ch < NCH - 1) { CP_WAIT(1); } else { CP_WAIT(0); }
        __syncthreads();
        if (ch + 2 < NCH) issue_chunk(ch + 2);

        const uint32_t aBase = sAu + (ch % NST) * ASTG;
        const uint32_t bBase = sBu + (ch % NST) * BSTG;

        if (ntW > 0) {
            #pragma unroll
            for (int ks = 0; ks < 2; ks++) {
                const uint32_t kloc = ks * 16;

                uint32_t af[4][4];
                #pragma unroll
                for (int mt = 0; mt < 4; mt++) {
                    if (mt < ntM) {
                        const uint32_t addr = aBase
                            + (mbase + mt * 16 + a_row) * SPITCH + (kloc + a_col) * 2;
                        asm volatile(
                            "ldmatrix.sync.aligned.m8n8.x4.shared.b16 {%0,%1,%2,%3}, [%4];"
                            : "=r"(af[mt][0]), "=r"(af[mt][1]),
                              "=r"(af[mt][2]), "=r"(af[mt][3])
                            : "r"(addr));
                    }
                }
                uint32_t bfr[5][2];
                #pragma unroll
                for (int nt = 0; nt < 5; nt++) {
                    if (nt < ntW) {
                        const uint32_t addr = bBase
                            + (warpN0 + nt * 8 + b_row) * SPITCH + (kloc + b_col) * 2;
                        asm volatile(
                            "ldmatrix.sync.aligned.m8n8.x2.shared.b16 {%0,%1}, [%2];"
                            : "=r"(bfr[nt][0]), "=r"(bfr[nt][1])
                            : "r"(addr));
                    }
                }
                #pragma unroll
                for (int nt = 0; nt < 5; nt++) {
                    if (nt < ntW) {
                        #pragma unroll
                        for (int mt = 0; mt < 4; mt++)
                            if (mt < ntM)
                                mma_16816(acc[mt][nt], af[mt], bfr[nt]);
                    }
                }
            }
        }
        // no trailing sync: next iteration's barrier protects stage reuse
    }

    // ---- Epilogue (len-skipped, trimmed M) ----
    #pragma unroll
    for (int mt = 0; mt < 4; mt++) {
        if (mt < ntM) {
            #pragma unroll
            for (int h = 0; h < 2; h++) {
                float m = -CUDART_INF_F;
                #pragma unroll
                for (int nt = 0; nt < 5; nt++) {
                    if (nt < ntW) {
                        #pragma unroll
                        for (int j = 0; j < 2; j++) {
                            const int c = warpN0 + nt * 8 + lanem * 2 + j;
                            if (c < len)
                                m = fmaxf(m, acc[mt][nt][h * 2 + j]);
                        }
                    }
                }
                m = fmaxf(m, __shfl_xor_sync(0xffffffffu, m, 1));
                m = fmaxf(m, __shfl_xor_sync(0xffffffffu, m, 2));
                if (lanem == 0)
                    rowmax2[mbase + mt * 16 + lane4 + 8 * h][wid & 1] = m;
            }
        }
    }

    #pragma unroll
    for (int nt = 0; nt < 5; nt++) {
        if (nt < ntW) {
            #pragma unroll
            for (int j = 0; j < 2; j++) {
                float m = -CUDART_INF_F;
                #pragma unroll
                for (int mt = 0; mt < 4; mt++) {
                    if (mt < ntM) {
                        #pragma unroll
                        for (int h = 0; h < 2; h++) {
                            const int r = mbase + mt * 16 + lane4 + 8 * h;
                            const float s = acc[mt][nt][h * 2 + j];
                            m = fmaxf(m, (r < V_) ? s : -CUDART_INF_F);
                        }
                    }
                }
                m = fmaxf(m, __shfl_xor_sync(0xffffffffu, m, 4));
                m = fmaxf(m, __shfl_xor_sync(0xffffffffu, m, 8));
                m = fmaxf(m, __shfl_xor_sync(0xffffffffu, m, 16));
                if (lane < 4) {
                    const int c = warpN0 + nt * 8 + lane * 2 + j;
                    colmax2[c][g] = m;
                }
            }
        }
    }
    __syncthreads();

    {
        float s = 0.f;
        if (tid < V_) {
            s = fmaxf(rowmax2[tid][0], rowmax2[tid][1]);
            if (len < T_) s = fmaxf(s, 0.0f);
        }
        #pragma unroll
        for (int off = 16; off; off >>= 1)
            s += __shfl_xor_sync(0xffffffffu, s, off);
        if (lane == 0) warpsum[wid] = s;
    }
    if (wid < 3) {
        const int c = wid * 32 + lane;
        float s = 0.f;
        if (c < len) {
            const float m01 = fmaxf(colmax2[c][0], colmax2[c][1]);
            const float m23 = fmaxf(colmax2[c][2], colmax2[c][3]);
            s = fmaxf(m01, m23);
        }
        #pragma unroll
        for (int off = 16; off; off >>= 1)
            s += __shfl_xor_sync(0xffffffffu, s, off);
        if (lane == 0) t2vpart[wid] = s;
    }
    __syncthreads();

    if (tid == 0) {
        float s1 = 0.f;
        #pragma unroll
        for (int t = 0; t < 8; t++) s1 += warpsum[t];
        out_v2t[b * Q_ + q] = s1 / (float)V_;
        out_t2v[b * Q_ + q] = (t2vpart[0] + t2vpart[1] + t2vpart[2]) / (float)len;
    }
}

// ===========================================================================
// kernel_launch
// ===========================================================================
extern "C" void kernel_launch(void* const* d_in, const int* in_sizes, int n_in,
                              void* d_out, int out_size)
{
    const float* visual_cls     = (const float*)d_in[0];
    const float* visual_tokens  = (const float*)d_in[1];
    const float* textual_cls    = (const float*)d_in[2];
    const float* textual_tokens = (const float*)d_in[3];
    const float* Wv_cls = (const float*)d_in[4];
    const float* bv_cls = (const float*)d_in[5];
    const float* Wt_cls = (const float*)d_in[6];
    const float* bt_cls = (const float*)d_in[7];
    const float* Wv_tok = (const float*)d_in[8];
    const float* bv_tok = (const float*)d_in[9];
    const float* Wt_tok = (const float*)d_in[10];
    const float* bt_tok = (const float*)d_in[11];
    const int*   tlen   = (const int*)d_in[12];

    float* out    = (float*)d_out;
    float* o_vcls = out;
    float* o_tcls = out + 96 * 512;
    float* o_t2v  = out + 2 * 96 * 512;
    float* o_v2t  = o_t2v + 96 * 96;

    float* vtok = nullptr;
    float* ttok = nullptr;
    __nv_bfloat16 *vtok_bf = nullptr, *ttok_bf = nullptr;
    __nv_bfloat16 *wv_bf = nullptr, *wt_bf = nullptr;
    cudaGetSymbolAddress((void**)&vtok, g_vtok);
    cudaGetSymbolAddress((void**)&ttok, g_ttok);
    cudaGetSymbolAddress((void**)&vtok_bf, g_vtok_bf);
    cudaGetSymbolAddress((void**)&ttok_bf, g_ttok_bf);
    cudaGetSymbolAddress((void**)&wv_bf, g_wv_bf);
    cudaGetSymbolAddress((void**)&wt_bf, g_wt_bf);

    // 0. token weights -> bf16 (single launch)
    weights_to_bf16_kernel<<<(2 * WN4 + 255) / 256, 256>>>(Wv_tok, Wt_tok,
                                                           wv_bf, wt_bf);
    // 1. cls projections (merged, exact fp32) -> output
    {
        dim3 grid(2, E_ / 64, 2);
        gemm_cls_kernel<<<grid, 256>>>(visual_cls,  Wv_cls, bv_cls, o_vcls,
                                       textual_cls, Wt_cls, bt_cls, o_tcls);
    }
    // 2. token projections -> fp32 scratch (bf16 tensor-core GEMM)
    {
        dim3 gv((VROWS + 127) / 128, E_ / 128);
        gemm_bf16_kernel<<<gv, 256>>>(visual_tokens, wv_bf, bv_tok, vtok, VROWS);
        dim3 gt((TROWS + 127) / 128, E_ / 128);
        gemm_bf16_kernel<<<gt, 256>>>(textual_tokens, wt_bf, bt_tok, ttok, TROWS);
    }
    // 3. L2 normalize -> bf16 (single launch for both)
    l2norm_bf16_kernel<<<(VROWS + TROWS + 7) / 8, 256>>>(vtok, vtok_bf,
                                                         ttok, ttok_bf);
    // 4. sim: len-skip + trimmed M + 3-stage cp.async, 1 barrier per chunk
    {
        dim3 grid(Q_, B_);
        sim_mma_kernel<<<grid, 256>>>(vtok_bf, ttok_bf, tlen, o_t2v, o_v2t);
    }
}